// round 11
// baseline (speedup 1.0000x reference)
#include <cuda_runtime.h>
#include <cuda_bf16.h>
#include <math.h>
#include <stdint.h>

// ---------------- problem constants ----------------
#define EDIM   768
#define NTOK   197
#define BSZ    16
#define ROWS   (BSZ*NTOK)      // 3152
#define MFEAT  256
#define FDIM   3072
#define NPATCH 196
#define NC     1000
#define NLAYER 12
#define KPAD   224             // 197 padded to mult of 32

#define SCAL  0.18995897f      // 768^{-1/4}
#define MSCL  0.0625f          // 256^{-1/2}
#define FEPS  1e-4f

typedef __nv_bfloat16 bf;

// ---------------- scratch (device globals; allocation-free) ----------------
__device__ float g_h   [ROWS*EDIM];
__device__ float g_lg  [ROWS*MFEAT];
__device__ float g_tok [BSZ*NPATCH*EDIM];
__device__ float g_part[2*ROWS*EDIM];
__device__ float g_diag[ROWS];
__device__ float g_qmax[ROWS];
__device__ float g_den [ROWS];
__device__ float g_ksum[BSZ*MFEAT];
__device__ float g_gmax[1];
__device__ float g_cls [BSZ*EDIM];

// bf16 hi/lo operand pairs
__device__ bf g_yh  [ROWS*EDIM],      g_yl  [ROWS*EDIM];
__device__ bf g_qfh [ROWS*MFEAT],     g_qfl [ROWS*MFEAT];
__device__ bf g_kfTh[BSZ*MFEAT*KPAD], g_kfTl[BSZ*MFEAT*KPAD];
__device__ bf g_yTh [BSZ*EDIM*KPAD],  g_yTl [BSZ*EDIM*KPAD];
__device__ bf g_kvTh[BSZ*EDIM*MFEAT], g_kvTl[BSZ*EDIM*MFEAT];
__device__ bf g_tmph[ROWS*FDIM],      g_tmpl[ROWS*FDIM];
__device__ bf g_pth [BSZ*NPATCH*768], g_ptl [BSZ*NPATCH*768];
__device__ bf g_pwh [EDIM*768],       g_pwl [EDIM*768];
__device__ bf g_pjh [NLAYER*MFEAT*EDIM], g_pjl [NLAYER*MFEAT*EDIM];
__device__ bf g_w1h [NLAYER*FDIM*EDIM],  g_w1l [NLAYER*FDIM*EDIM];
__device__ bf g_w2h [NLAYER*EDIM*FDIM],  g_w2l [NLAYER*EDIM*FDIM];

// ---------------- helpers ----------------
__device__ __forceinline__ void bsplit(float v, bf& h, bf& l)
{
    h = __float2bfloat16(v);
    l = __float2bfloat16(v - __bfloat162float(h));
}

__device__ __forceinline__ uint32_t smem_addr(const void* p)
{
    uint32_t a;
    asm("{ .reg .u64 t; cvta.to.shared.u64 t, %1; cvt.u32.u64 %0, t; }"
        : "=r"(a) : "l"(p));
    return a;
}

__device__ __forceinline__ void mma_bf16(float* c, const uint32_t* a, const uint32_t* b)
{
    asm volatile(
        "mma.sync.aligned.m16n8k16.row.col.f32.bf16.bf16.f32 "
        "{%0,%1,%2,%3}, {%4,%5,%6,%7}, {%8,%9}, {%0,%1,%2,%3};"
        : "+f"(c[0]), "+f"(c[1]), "+f"(c[2]), "+f"(c[3])
        : "r"(a[0]), "r"(a[1]), "r"(a[2]), "r"(a[3]), "r"(b[0]), "r"(b[1]));
}
__device__ __forceinline__ void ldsm_x4(uint32_t* r, uint32_t addr)
{
    asm volatile("ldmatrix.sync.aligned.m8n8.x4.shared.b16 {%0,%1,%2,%3}, [%4];"
                 : "=r"(r[0]), "=r"(r[1]), "=r"(r[2]), "=r"(r[3]) : "r"(addr));
}
__device__ __forceinline__ void ldsm_x2(uint32_t* r, uint32_t addr)
{
    asm volatile("ldmatrix.sync.aligned.m8n8.x2.shared.b16 {%0,%1}, [%2];"
                 : "=r"(r[0]), "=r"(r[1]) : "r"(addr));
}

// ================= bf16-pair reg-staged mma GEMM =================
// C[M, N=grid.x*128] = (Ah+Al)[M,klen] @ (Bh+Bl)[N,klen]^T  (K-major bf16 pairs)
// flags: 1=+bias[n] 2=gelu 4=accum into C 8=/rowdiv[z*sdiv+m] 16=write bf16 pair (Ch,Cl)
#define SP 40   // smem pitch in halfs (80 bytes): conflict-free for ldmatrix

__global__ void __launch_bounds__(256) mma_gemm(
    const bf* __restrict__ Ah, const bf* __restrict__ Al,
    const bf* __restrict__ Bh, const bf* __restrict__ Bl,
    float* __restrict__ C, bf* __restrict__ Ch, bf* __restrict__ Cl,
    int M, int ldA, int ldB, int ldC,
    long long sA, long long sB, long long sC,
    int kstart, int kzs, int klen,
    const float* __restrict__ bias, const float* __restrict__ rowdiv, int sdiv, int flags)
{
    __shared__ __align__(16) bf sAh[128 * SP];
    __shared__ __align__(16) bf sAl[128 * SP];
    __shared__ __align__(16) bf sBh[128 * SP];
    __shared__ __align__(16) bf sBl[128 * SP];

    int tid = threadIdx.x;
    int wid = tid >> 5, lane = tid & 31;
    int m0 = blockIdx.y * 128, n0 = blockIdx.x * 128, z = blockIdx.z;
    int warpM = wid >> 2;          // 0..1 -> 64 rows
    int warpN = wid & 3;           // 0..3 -> 32 cols
    int qr = lane >> 2;
    int qc = (lane & 3) * 2;

    const bf* Abh = Ah + (long long)z * sA + kstart + (long long)z * kzs;
    const bf* Abl = Al + (long long)z * sA + kstart + (long long)z * kzs;
    const bf* Bbh = Bh + (long long)z * sB + kstart + (long long)z * kzs;
    const bf* Bbl = Bl + (long long)z * sB + kstart + (long long)z * kzs;

    // load geometry: row = tid>>1, 32B chunk at halfs cb within the 64B (32-half) row slab
    int lrow = tid >> 1;
    int cb   = (tid & 1) * 16;
    int gm   = m0 + lrow;
    int gmc  = (gm < M) ? gm : (M - 1);
    int gn   = n0 + lrow;
    int so   = lrow * SP + cb;     // smem half-offset

    // ldmatrix lane offsets (bytes)
    uint32_t AhB = smem_addr(sAh), AlB = smem_addr(sAl);
    uint32_t BhB = smem_addr(sBh), BlB = smem_addr(sBl);
    uint32_t aoff = (uint32_t)((warpM * 64 + (lane & 15)) * 80 + ((lane >> 4) << 4));
    uint32_t boff = (uint32_t)((warpN * 32 + (lane & 7)) * 80 + (((lane >> 3) & 1) << 4));

    float acc[4][4][4];
#pragma unroll
    for (int i = 0; i < 4; i++)
#pragma unroll
        for (int j = 0; j < 4; j++)
#pragma unroll
            for (int r = 0; r < 4; r++) acc[i][j][r] = 0.f;

    int ktn = klen >> 5;

    uint4 rah[2], ral[2], rbh[2], rbl[2];
#define LOADREG(KT) do { \
    long long ko = ((long long)(KT) << 5) + cb; \
    const uint4* pa  = (const uint4*)(Abh + (long long)gmc * ldA + ko); \
    const uint4* pal = (const uint4*)(Abl + (long long)gmc * ldA + ko); \
    const uint4* pb  = (const uint4*)(Bbh + (long long)gn * ldB + ko); \
    const uint4* pbl = (const uint4*)(Bbl + (long long)gn * ldB + ko); \
    rah[0] = pa[0];  rah[1] = pa[1]; \
    ral[0] = pal[0]; ral[1] = pal[1]; \
    rbh[0] = pb[0];  rbh[1] = pb[1]; \
    rbl[0] = pbl[0]; rbl[1] = pbl[1]; \
} while (0)

    LOADREG(0);

    for (int kt = 0; kt < ktn; kt++) {
        __syncthreads();
        *(uint4*)&sAh[so] = rah[0]; *(uint4*)&sAh[so + 8] = rah[1];
        *(uint4*)&sAl[so] = ral[0]; *(uint4*)&sAl[so + 8] = ral[1];
        *(uint4*)&sBh[so] = rbh[0]; *(uint4*)&sBh[so + 8] = rbh[1];
        *(uint4*)&sBl[so] = rbl[0]; *(uint4*)&sBl[so + 8] = rbl[1];
        __syncthreads();
        if (kt + 1 < ktn) LOADREG(kt + 1);
#pragma unroll
        for (int ks = 0; ks < 2; ks++) {
            uint32_t kbyte = (uint32_t)(ks * 32);
            uint32_t bhf[4][2], blf[4][2];
#pragma unroll
            for (int nt = 0; nt < 4; nt++) {
                uint32_t bo = boff + (uint32_t)(nt * 8 * 80) + kbyte;
                ldsm_x2(bhf[nt], BhB + bo);
                ldsm_x2(blf[nt], BlB + bo);
            }
#pragma unroll
            for (int mt = 0; mt < 4; mt++) {
                uint32_t ao = aoff + (uint32_t)(mt * 16 * 80) + kbyte;
                uint32_t ahf[4], alf[4];
                ldsm_x4(ahf, AhB + ao);
                ldsm_x4(alf, AlB + ao);
#pragma unroll
                for (int nt = 0; nt < 4; nt++) {
                    mma_bf16(acc[mt][nt], ahf, bhf[nt]);
                    mma_bf16(acc[mt][nt], ahf, blf[nt]);
                    mma_bf16(acc[mt][nt], alf, bhf[nt]);
                }
            }
        }
    }
#undef LOADREG

    // ---- epilogue ----
#pragma unroll
    for (int mt = 0; mt < 4; mt++) {
        int r0 = m0 + warpM * 64 + mt * 16 + qr;
        int r1 = r0 + 8;
        bool ok0 = r0 < M, ok1 = r1 < M;
        float dv0 = 1.f, dv1 = 1.f;
        if (flags & 8) {
            if (ok0) dv0 = 1.f / rowdiv[(long long)z * sdiv + r0];
            if (ok1) dv1 = 1.f / rowdiv[(long long)z * sdiv + r1];
        }
#pragma unroll
        for (int nt = 0; nt < 4; nt++) {
            int col = n0 + warpN * 32 + nt * 8 + qc;
            float b0 = 0.f, b1 = 0.f;
            if (flags & 1) { b0 = bias[col]; b1 = bias[col + 1]; }
#pragma unroll
            for (int half = 0; half < 2; half++) {
                bool ok = half ? ok1 : ok0;
                if (!ok) continue;
                int r = half ? r1 : r0;
                long long base = (long long)z * sC + (long long)r * ldC + col;
                float v0 = acc[mt][nt][half * 2 + 0] + b0;
                float v1 = acc[mt][nt][half * 2 + 1] + b1;
                if (flags & 2) {
                    v0 = 0.5f * v0 * (1.f + erff(v0 * 0.70710678118654752f));
                    v1 = 0.5f * v1 * (1.f + erff(v1 * 0.70710678118654752f));
                }
                if (flags & 16) {
                    bf h0, l0, h1, l1;
                    bsplit(v0, h0, l0); bsplit(v1, h1, l1);
                    Ch[base] = h0; Ch[base + 1] = h1;
                    Cl[base] = l0; Cl[base + 1] = l1;
                } else {
                    float dv = half ? dv1 : dv0;
                    if (flags & 8) { v0 *= dv; v1 *= dv; }
                    if (flags & 4) { v0 += C[base]; v1 += C[base + 1]; }
                    C[base] = v0; C[base + 1] = v1;
                }
            }
        }
    }
}

// ================= fallback SGEMM (head only) =================
__global__ void __launch_bounds__(256) gemm_kernel(
    const float* __restrict__ A, const float* __restrict__ B, float* __restrict__ C,
    int M, int N, int K,
    const float* __restrict__ bias, int flags)
{
    __shared__ __align__(16) float As[8][128];
    __shared__ __align__(16) float Bs[8][128];
    int tid = threadIdx.x;
    int m0 = blockIdx.y * 128;
    int n0 = blockIdx.x * 128;
    int tx = tid & 15, ty = tid >> 4;
    float acc[8][8];
#pragma unroll
    for (int i = 0; i < 8; i++)
#pragma unroll
        for (int j = 0; j < 8; j++) acc[i][j] = 0.f;
    for (int k0 = 0; k0 < K; k0 += 8) {
#pragma unroll
        for (int i = 0; i < 4; i++) {
            int l = tid + i * 256;
            int mm = l >> 3, kk = l & 7;
            int gk = k0 + kk, gm = m0 + mm;
            As[kk][mm] = (gk < K && gm < M) ? A[(long long)gm * K + gk] : 0.f;
        }
#pragma unroll
        for (int i = 0; i < 4; i++) {
            int l = tid + i * 256;
            int kk = l >> 7, nn = l & 127;
            int gk = k0 + kk, gn = n0 + nn;
            Bs[kk][nn] = (gk < K && gn < N) ? B[(long long)gk * N + gn] : 0.f;
        }
        __syncthreads();
#pragma unroll
        for (int k = 0; k < 8; k++) {
            float4 a0 = *(const float4*)&As[k][ty * 4];
            float4 a1 = *(const float4*)&As[k][ty * 4 + 64];
            float4 b0 = *(const float4*)&Bs[k][tx * 4];
            float4 b1 = *(const float4*)&Bs[k][tx * 4 + 64];
            float af[8] = {a0.x, a0.y, a0.z, a0.w, a1.x, a1.y, a1.z, a1.w};
            float bf_[8] = {b0.x, b0.y, b0.z, b0.w, b1.x, b1.y, b1.z, b1.w};
#pragma unroll
            for (int i = 0; i < 8; i++)
#pragma unroll
                for (int j = 0; j < 8; j++) acc[i][j] += af[i] * bf_[j];
        }
        __syncthreads();
    }
#pragma unroll
    for (int i = 0; i < 8; i++) {
        int gm = m0 + ((i < 4) ? ty * 4 + i : 64 + ty * 4 + (i - 4));
        if (gm >= M) continue;
        float* crow = C + (long long)gm * N;
#pragma unroll
        for (int j = 0; j < 8; j++) {
            int gn = n0 + ((j < 4) ? tx * 4 + j : 64 + tx * 4 + (j - 4));
            if (gn >= N) continue;
            float v = acc[i][j];
            if (flags & 1) v += bias[gn];
            crow[gn] = v;
        }
    }
}

// ================= layernorm: warp per row; fp32 or bf16-pair output =================
__global__ void ln_kernel(const float* __restrict__ X, long long ldx,
                          float* __restrict__ Y, bf* __restrict__ Yh, bf* __restrict__ Yl,
                          long long ldy,
                          const float* __restrict__ g, const float* __restrict__ b,
                          float* __restrict__ diag, int nrows)
{
    int w = blockIdx.x * (blockDim.x >> 5) + (threadIdx.x >> 5);
    int lane = threadIdx.x & 31;
    if (w >= nrows) return;
    const float4* x = (const float4*)(X + (long long)w * ldx);
    float4 v[6];
    float s1 = 0.f, s2 = 0.f;
#pragma unroll
    for (int i = 0; i < 6; i++) {
        v[i] = x[lane + 32 * i];
        s1 += v[i].x + v[i].y + v[i].z + v[i].w;
        s2 += v[i].x * v[i].x + v[i].y * v[i].y + v[i].z * v[i].z + v[i].w * v[i].w;
    }
#pragma unroll
    for (int o = 16; o > 0; o >>= 1) {
        s1 += __shfl_xor_sync(0xffffffffu, s1, o);
        s2 += __shfl_xor_sync(0xffffffffu, s2, o);
    }
    float mu  = s1 * (1.0f / 768.0f);
    float var = s2 * (1.0f / 768.0f) - mu * mu;
    float inv = rsqrtf(var + 1e-5f);
    const float4* g4 = (const float4*)g;
    const float4* b4 = (const float4*)b;
    float d = 0.f;
#pragma unroll
    for (int i = 0; i < 6; i++) {
        float4 gv = g4[lane + 32 * i], bv = b4[lane + 32 * i], o;
        o.x = (v[i].x - mu) * inv * gv.x + bv.x;
        o.y = (v[i].y - mu) * inv * gv.y + bv.y;
        o.z = (v[i].z - mu) * inv * gv.z + bv.z;
        o.w = (v[i].w - mu) * inv * gv.w + bv.w;
        d += o.x * o.x + o.y * o.y + o.z * o.z + o.w * o.w;
        long long e = (long long)w * ldy + (lane + 32 * i) * 4;
        if (Yh) {
            bf h0, l0, h1, l1, h2, l2, h3, l3;
            bsplit(o.x, h0, l0); bsplit(o.y, h1, l1);
            bsplit(o.z, h2, l2); bsplit(o.w, h3, l3);
            __nv_bfloat162 ha = __halves2bfloat162(h0, h1);
            __nv_bfloat162 hb = __halves2bfloat162(h2, h3);
            __nv_bfloat162 la = __halves2bfloat162(l0, l1);
            __nv_bfloat162 lb = __halves2bfloat162(l2, l3);
            *(__nv_bfloat162*)&Yh[e] = ha; *(__nv_bfloat162*)&Yh[e + 2] = hb;
            *(__nv_bfloat162*)&Yl[e] = la; *(__nv_bfloat162*)&Yl[e + 2] = lb;
        } else {
            *(float4*)&Y[e] = o;
        }
    }
    if (diag) {
#pragma unroll
        for (int o = 16; o > 0; o >>= 1) d += __shfl_xor_sync(0xffffffffu, d, o);
        if (lane == 0) diag[w] = 0.5f * SCAL * SCAL * d;
    }
}

// ================= performer helpers =================
__global__ void lg_rowmax_kernel(float* __restrict__ lg, const float* __restrict__ diag,
                                 float* __restrict__ qmax)
{
    int row = blockIdx.x;
    int tid = threadIdx.x;
    long long idx = (long long)row * MFEAT + tid;
    float v = lg[idx] * SCAL - diag[row];
    lg[idx] = v;
    __shared__ float red[8];
    float m = v;
#pragma unroll
    for (int o = 16; o > 0; o >>= 1) m = fmaxf(m, __shfl_down_sync(0xffffffffu, m, o));
    int w = tid >> 5, lane = tid & 31;
    if (lane == 0) red[w] = m;
    __syncthreads();
    if (tid == 0) {
        float a = red[0];
        for (int i = 1; i < 8; i++) a = fmaxf(a, red[i]);
        qmax[row] = a;
    }
}

__global__ void gmax_kernel(const float* __restrict__ qmax, float* __restrict__ gmax)
{
    int tid = threadIdx.x;
    float m = -1e30f;
    for (int i = tid; i < ROWS; i += 256) m = fmaxf(m, qmax[i]);
    __shared__ float red[8];
#pragma unroll
    for (int o = 16; o > 0; o >>= 1) m = fmaxf(m, __shfl_down_sync(0xffffffffu, m, o));
    int w = tid >> 5, lane = tid & 31;
    if (lane == 0) red[w] = m;
    __syncthreads();
    if (tid == 0) {
        float a = red[0];
        for (int i = 1; i < 8; i++) a = fmaxf(a, red[i]);
        gmax[0] = a;
    }
}

__global__ void feat_kernel(const float* __restrict__ lg, const float* __restrict__ qmax,
                            const float* __restrict__ gmax,
                            bf* __restrict__ qfh, bf* __restrict__ qfl,
                            bf* __restrict__ kfTh, bf* __restrict__ kfTl)
{
    long long i = (long long)blockIdx.x * 256 + threadIdx.x;
    if (i >= (long long)ROWS * MFEAT) return;
    int tg = (int)(i >> 8);
    int m = (int)(i & 255);
    int b = tg / NTOK;
    int t = tg - b * NTOK;
    float v = lg[i];
    float q = expf(v - qmax[tg]) * MSCL + FEPS;
    float k = expf(v - gmax[0]) * MSCL + FEPS;
    bf h, l;
    bsplit(q, h, l); qfh[i] = h; qfl[i] = l;
    long long ki = ((long long)(b * MFEAT + m)) * KPAD + t;
    bsplit(k, h, l); kfTh[ki] = h; kfTl[ki] = l;
}

__global__ void ksum_kernel(const bf* __restrict__ kfTh, const bf* __restrict__ kfTl,
                            float* __restrict__ ksum)
{
    int w = (blockIdx.x * blockDim.x + threadIdx.x) >> 5;
    int lane = threadIdx.x & 31;
    if (w >= BSZ * MFEAT) return;
    const bf* ph = kfTh + (long long)w * KPAD;
    const bf* pl = kfTl + (long long)w * KPAD;
    float s = 0.f;
#pragma unroll
    for (int t = lane; t < KPAD; t += 32)
        s += __bfloat162float(ph[t]) + __bfloat162float(pl[t]);
#pragma unroll
    for (int o = 16; o > 0; o >>= 1) s += __shfl_down_sync(0xffffffffu, s, o);
    if (lane == 0) ksum[w] = s;
}

__global__ void den_kernel(const bf* __restrict__ qfh, const bf* __restrict__ qfl,
                           const float* __restrict__ ksum, float* __restrict__ den)
{
    int warp = (blockIdx.x * blockDim.x + threadIdx.x) >> 5;
    int lane = threadIdx.x & 31;
    if (warp >= ROWS) return;
    int b = warp / NTOK;
    const bf* qh = qfh + (long long)warp * MFEAT;
    const bf* ql = qfl + (long long)warp * MFEAT;
    const float* ks = ksum + b * MFEAT;
    float s = 0.f;
#pragma unroll
    for (int m = lane; m < MFEAT; m += 32)
        s += (__bfloat162float(qh[m]) + __bfloat162float(ql[m])) * ks[m];
#pragma unroll
    for (int o = 16; o > 0; o >>= 1) s += __shfl_down_sync(0xffffffffu, s, o);
    if (lane == 0) den[warp] = s;
}

// ================= transposes / converts =================
__global__ void transpose_pair(const bf* __restrict__ ih, const bf* __restrict__ il,
                               bf* __restrict__ oh, bf* __restrict__ ol,
                               int R, int Ccol, int ldo, long long sin, long long sout)
{
    __shared__ uint32_t t[32][33];
    const bf* iph = ih + (long long)blockIdx.z * sin;
    const bf* ipl = il + (long long)blockIdx.z * sin;
    bf* oph = oh + (long long)blockIdx.z * sout;
    bf* opl = ol + (long long)blockIdx.z * sout;
    int c0 = blockIdx.x * 32, r0 = blockIdx.y * 32;
    int tx = threadIdx.x, ty = threadIdx.y;
#pragma unroll
    for (int k = 0; k < 4; k++) {
        int r = r0 + ty + 8 * k;
        if (r < R && c0 + tx < Ccol) {
            long long idx = (long long)r * Ccol + c0 + tx;
            uint32_t hv = (uint32_t)*(const uint16_t*)&iph[idx];
            uint32_t lv = (uint32_t)*(const uint16_t*)&ipl[idx];
            t[ty + 8 * k][tx] = hv | (lv << 16);
        }
    }
    __syncthreads();
#pragma unroll
    for (int k = 0; k < 4; k++) {
        int c = c0 + ty + 8 * k;
        int r = r0 + tx;
        if (c < Ccol && r < R) {
            uint32_t v = t[tx][ty + 8 * k];
            long long idx = (long long)c * ldo + r;
            *(uint16_t*)&oph[idx] = (uint16_t)(v & 0xffff);
            *(uint16_t*)&opl[idx] = (uint16_t)(v >> 16);
        }
    }
}

__global__ void transpose_convert(const float* __restrict__ in,
                                  bf* __restrict__ oh, bf* __restrict__ ol,
                                  int R, int Ccol, long long sin, long long sout)
{
    __shared__ float t[32][33];
    const float* ip = in + (long long)blockIdx.z * sin;
    bf* oph = oh + (long long)blockIdx.z * sout;
    bf* opl = ol + (long long)blockIdx.z * sout;
    int c0 = blockIdx.x * 32, r0 = blockIdx.y * 32;
    int tx = threadIdx.x, ty = threadIdx.y;
#pragma unroll
    for (int k = 0; k < 4; k++) {
        int r = r0 + ty + 8 * k;
        if (r < R && c0 + tx < Ccol)
            t[ty + 8 * k][tx] = ip[(long long)r * Ccol + c0 + tx];
    }
    __syncthreads();
#pragma unroll
    for (int k = 0; k < 4; k++) {
        int c = c0 + ty + 8 * k;
        int r = r0 + tx;
        if (c < Ccol && r < R) {
            bf h, l;
            bsplit(t[tx][ty + 8 * k], h, l);
            long long idx = (long long)c * R + r;
            oph[idx] = h; opl[idx] = l;
        }
    }
}

__global__ void convert_pair(const float* __restrict__ in,
                             bf* __restrict__ oh, bf* __restrict__ ol, long long n)
{
    long long i = (long long)blockIdx.x * 256 + threadIdx.x;
    if (i >= n) return;
    bf h, l;
    bsplit(in[i], h, l);
    oh[i] = h; ol[i] = l;
}

// ================= misc elementwise =================
__global__ void im2col_kernel(const float* __restrict__ x,
                              bf* __restrict__ pth, bf* __restrict__ ptl)
{
    long long i = (long long)blockIdx.x * 256 + threadIdx.x;
    if (i >= (long long)BSZ * NPATCH * 768) return;
    int kidx = (int)(i % 768);
    int p    = (int)(i / 768);
    int pj = kidx & 15, pi = (kidx >> 4) & 15, c = kidx >> 8;
    int gj = p % 14;
    int t  = p / 14;
    int gi = t % 14;
    int b  = t / 14;
    float v = x[(((long long)(b * 3 + c) * 224 + gi * 16 + pi) * 224) + gj * 16 + pj];
    bf h, l;
    bsplit(v, h, l);
    pth[i] = h; ptl[i] = l;
}

__global__ void assemble_kernel(const float* __restrict__ tok, const float* __restrict__ cls_tok,
                                const float* __restrict__ pos, float* __restrict__ h)
{
    long long i = (long long)blockIdx.x * 256 + threadIdx.x;
    if (i >= (long long)ROWS * EDIM) return;
    int e = (int)(i % EDIM);
    int t = (int)(i / EDIM);
    int n = t % NTOK;
    int b = t / NTOK;
    float v = (n == 0) ? cls_tok[e] : tok[(long long)(b * NPATCH + n - 1) * EDIM + e];
    h[i] = v + pos[(long long)n * EDIM + e];
}

__global__ void combine_kernel(const float* __restrict__ part, const float* __restrict__ b2,
                               float* __restrict__ h)
{
    long long i = (long long)blockIdx.x * 256 + threadIdx.x;
    if (i >= (long long)ROWS * EDIM) return;
    int e = (int)(i % EDIM);
    h[i] += part[i] + part[(long long)ROWS * EDIM + i] + b2[e];
}

// ================= host =================
static inline void* symv(const void* s)
{
    void* p = nullptr;
    cudaGetSymbolAddress(&p, s);
    return p;
}

extern "C" void kernel_launch(void* const* d_in, const int* in_sizes, int n_in,
                              void* d_out, int out_size)
{
    const float* x       = (const float*)d_in[0];
    const float* cls_tok = (const float*)d_in[1];
    const float* pos_emb = (const float*)d_in[2];
    const float* patch_w = (const float*)d_in[3];
    const float* patch_b = (const float*)d_in[4];
    const float* ln1_g   = (const float*)d_in[5];
    const float* ln1_b   = (const float*)d_in[6];
    const float* proj    = (const float*)d_in[7];
    const float* ln2_g   = (const float*)d_in[8];
    const float* ln2_b   = (const float*)d_in[9];
    const float* w1      = (const float*)d_in[10];
    const float* b1      = (const float*)d_in[11];
    const float* w2      = (const float*)d_in[12];
    const float* b2      = (const float*)d_in[13];
    const float* lnf_g   = (const float*)d_in[14];
    const float* lnf_b   = (const float*)d_in[15];
    const float* head_w  = (const float*)d_in[16];
    const float* head_b  = (const float*)d_in[17];
    float* out = (float*)d_out;

    float* h    = (float*)symv(g_h);
    float* lg   = (float*)symv(g_lg);
    float* tok  = (float*)symv(g_tok);
    float* part = (float*)symv(g_part);
    float* diag = (float*)symv(g_diag);
    float* qmax = (float*)symv(g_qmax);
    float* den  = (float*)symv(g_den);
    float* ksum = (float*)symv(g_ksum);
    float* gmax = (float*)symv(g_gmax);
    float* clsb = (float*)symv(g_cls);

    bf* yh   = (bf*)symv(g_yh);   bf* yl   = (bf*)symv(g_yl);
    bf* qfh  = (bf*)symv(g_qfh);  bf* qfl  = (bf*)symv(g_qfl);
    bf* kfTh = (bf*)symv(g_kfTh); bf* kfTl = (bf*)symv(g_kfTl);
    bf* yTh  = (bf*)symv(g_yTh);  bf* yTl  = (bf*)symv(g_yTl);
    bf* kvTh = (bf*)symv(g_kvTh); bf* kvTl = (bf*)symv(g_kvTl);
    bf* tmph = (bf*)symv(g_tmph); bf* tmpl = (bf*)symv(g_tmpl);
    bf* pth  = (bf*)symv(g_pth);  bf* ptl  = (bf*)symv(g_ptl);
    bf* pwh  = (bf*)symv(g_pwh);  bf* pwl  = (bf*)symv(g_pwl);
    bf* pjh  = (bf*)symv(g_pjh);  bf* pjl  = (bf*)symv(g_pjl);
    bf* w1h  = (bf*)symv(g_w1h);  bf* w1l  = (bf*)symv(g_w1l);
    bf* w2h  = (bf*)symv(g_w2h);  bf* w2l  = (bf*)symv(g_w2l);

    // --- weight conversions ---
    {
        long long npw = (long long)EDIM * 768;
        convert_pair<<<(unsigned)((npw + 255) / 256), 256>>>(patch_w, pwh, pwl, npw);
        long long npj = (long long)NLAYER * MFEAT * EDIM;
        convert_pair<<<(unsigned)((npj + 255) / 256), 256>>>(proj, pjh, pjl, npj);
        dim3 blk(32, 8);
        // w1 [l][768][3072] -> [l][3072][768]
        transpose_convert<<<dim3(96, 24, NLAYER), blk>>>(w1, w1h, w1l,
            EDIM, FDIM, (long long)EDIM * FDIM, (long long)EDIM * FDIM);
        // w2 [l][3072][768] -> [l][768][3072]
        transpose_convert<<<dim3(24, 96, NLAYER), blk>>>(w2, w2h, w2l,
            FDIM, EDIM, (long long)EDIM * FDIM, (long long)EDIM * FDIM);
    }

    // --- patch embedding ---
    {
        long long tot = (long long)BSZ * NPATCH * 768;
        im2col_kernel<<<(unsigned)((tot + 255) / 256), 256>>>(x, pth, ptl);
        mma_gemm<<<dim3(6, 25, 1), 256>>>(pth, ptl, pwh, pwl,
            tok, nullptr, nullptr,
            BSZ * NPATCH, 768, 768, EDIM, 0, 0, 0, 0, 0, 768,
            patch_b, nullptr, 0, 1);
        long long ht = (long long)ROWS * EDIM;
        assemble_kernel<<<(unsigned)((ht + 255) / 256), 256>>>(tok, cls_tok, pos_emb, h);
    }

    for (int l = 0; l < NLAYER; l++) {
        long long pjo = (long long)l * MFEAT * EDIM;
        long long wo  = (long long)l * EDIM * FDIM;
        // LN1 -> y pair (+diag)
        ln_kernel<<<(ROWS + 7) / 8, 256>>>(h, EDIM, nullptr, yh, yl, EDIM,
            ln1_g + l * EDIM, ln1_b + l * EDIM, diag, ROWS);
        // logits = y @ proj^T -> lg fp32
        mma_gemm<<<dim3(2, 25, 1), 256>>>(yh, yl, pjh + pjo, pjl + pjo,
            lg, nullptr, nullptr,
            ROWS, EDIM, EDIM, MFEAT, 0, 0, 0, 0, 0, EDIM,
            nullptr, nullptr, 0, 0);
        lg_rowmax_kernel<<<ROWS, 256>>>(lg, diag, qmax);
        gmax_kernel<<<1, 256>>>(qmax, gmax);
        feat_kernel<<<(ROWS * MFEAT + 255) / 256, 256>>>(lg, qmax, gmax, qfh, qfl, kfTh, kfTl);
        ksum_kernel<<<(BSZ * MFEAT * 32 + 255) / 256, 256>>>(kfTh, kfTl, ksum);
        // yT pair
        transpose_pair<<<dim3(24, 7, BSZ), dim3(32, 8)>>>(yh, yl, yTh, yTl,
            NTOK, EDIM, KPAD, (long long)NTOK * EDIM, (long long)EDIM * KPAD);
        // kvT = yT @ kfT^T -> pair
        mma_gemm<<<dim3(2, 6, BSZ), 256>>>(yTh, yTl, kfTh, kfTl,
            nullptr, kvTh, kvTl,
            EDIM, KPAD, KPAD, MFEAT,
            (long long)EDIM * KPAD, (long long)MFEAT * KPAD, (long long)EDIM * MFEAT,
            0, 0, KPAD, nullptr, nullptr, 0, 16);
        den_kernel<<<(ROWS + 7) / 8, 256>>>(qfh, qfl, ksum, den);
        // h += (qf @ kvT^T) / den
        mma_gemm<<<dim3(6, 2, BSZ), 256>>>(qfh, qfl, kvTh, kvTl,
            h, nullptr, nullptr,
            NTOK, MFEAT, MFEAT, EDIM,
            (long long)NTOK * MFEAT, (long long)EDIM * MFEAT, (long long)NTOK * EDIM,
            0, 0, MFEAT, nullptr, den, NTOK, 4 | 8);
        // LN2 -> y pair
        ln_kernel<<<(ROWS + 7) / 8, 256>>>(h, EDIM, nullptr, yh, yl, EDIM,
            ln2_g + l * EDIM, ln2_b + l * EDIM, nullptr, ROWS);
        // hid = gelu(y @ w1 + b1) -> tmp pair
        mma_gemm<<<dim3(24, 25, 1), 256>>>(yh, yl, w1h + wo, w1l + wo,
            nullptr, tmph, tmpl,
            ROWS, EDIM, EDIM, FDIM, 0, 0, 0, 0, 0, EDIM,
            b1 + l * FDIM, nullptr, 0, 1 | 2 | 16);
        // part[z] = hid[:, z*1536:] @ w2T[:, z*1536:]^T (split-K over 2)
        mma_gemm<<<dim3(6, 25, 2), 256>>>(tmph, tmpl, w2h + wo, w2l + wo,
            part, nullptr, nullptr,
            ROWS, FDIM, FDIM, EDIM, 0, 0, (long long)ROWS * EDIM,
            0, FDIM / 2, FDIM / 2, nullptr, nullptr, 0, 0);
        combine_kernel<<<(ROWS * EDIM + 255) / 256, 256>>>(part, b2 + l * EDIM, h);
    }

    // final LN on CLS tokens + head
    ln_kernel<<<2, 256>>>(h, (long long)NTOK * EDIM, clsb, nullptr, nullptr, EDIM,
        lnf_g, lnf_b, nullptr, BSZ);
    {
        dim3 grid(8, 1, 1);
        gemm_kernel<<<grid, 256>>>(clsb, head_w, out,
            BSZ, NC, EDIM, head_b, 1);
    }
}

// round 12
// speedup vs baseline: 1.4289x; 1.4289x over previous
#include <cuda_runtime.h>
#include <cuda_bf16.h>
#include <math.h>
#include <stdint.h>

// ---------------- problem constants ----------------
#define EDIM   768
#define NTOK   197
#define BSZ    16
#define ROWS   (BSZ*NTOK)      // 3152
#define MFEAT  256
#define FDIM   3072
#define NPATCH 196
#define NC     1000
#define NLAYER 12
#define KPAD   224             // 197 padded to mult of 32

#define SCAL  0.18995897f      // 768^{-1/4}
#define MSCL  0.0625f          // 256^{-1/2}
#define FEPS  1e-4f

typedef __nv_bfloat16 bf;

// ---------------- scratch (device globals; allocation-free) ----------------
__device__ float g_h   [ROWS*EDIM];
__device__ float g_lg  [ROWS*MFEAT];
__device__ float g_tok [BSZ*NPATCH*EDIM];
__device__ float g_part[2*ROWS*EDIM];
__device__ float g_diag[ROWS];
__device__ float g_qmax[ROWS];
__device__ float g_den [ROWS];
__device__ float g_ksum[BSZ*MFEAT];
__device__ float g_gmax[1];
__device__ float g_cls [BSZ*EDIM];

// bf16 hi/lo operand pairs
__device__ bf g_yh  [ROWS*EDIM],      g_yl  [ROWS*EDIM];
__device__ bf g_qfh [ROWS*MFEAT],     g_qfl [ROWS*MFEAT];
__device__ bf g_kfTh[BSZ*MFEAT*KPAD], g_kfTl[BSZ*MFEAT*KPAD];
__device__ bf g_yTh [BSZ*EDIM*KPAD],  g_yTl [BSZ*EDIM*KPAD];
__device__ bf g_kvTh[BSZ*EDIM*MFEAT], g_kvTl[BSZ*EDIM*MFEAT];
__device__ bf g_tmph[ROWS*FDIM],      g_tmpl[ROWS*FDIM];
__device__ bf g_pth [BSZ*NPATCH*768], g_ptl [BSZ*NPATCH*768];
__device__ bf g_pwh [EDIM*768],       g_pwl [EDIM*768];
__device__ bf g_pjh [NLAYER*MFEAT*EDIM], g_pjl [NLAYER*MFEAT*EDIM];
__device__ bf g_w1h [NLAYER*FDIM*EDIM],  g_w1l [NLAYER*FDIM*EDIM];
__device__ bf g_w2h [NLAYER*EDIM*FDIM],  g_w2l [NLAYER*EDIM*FDIM];

// ---------------- helpers ----------------
__device__ __forceinline__ void bsplit(float v, bf& h, bf& l)
{
    h = __float2bfloat16(v);
    l = __float2bfloat16(v - __bfloat162float(h));
}

__device__ __forceinline__ uint32_t smem_addr(const void* p)
{
    uint32_t a;
    asm("{ .reg .u64 t; cvta.to.shared.u64 t, %1; cvt.u32.u64 %0, t; }"
        : "=r"(a) : "l"(p));
    return a;
}

__device__ __forceinline__ void mma_bf16(float* c, const uint32_t* a, const uint32_t* b)
{
    asm volatile(
        "mma.sync.aligned.m16n8k16.row.col.f32.bf16.bf16.f32 "
        "{%0,%1,%2,%3}, {%4,%5,%6,%7}, {%8,%9}, {%0,%1,%2,%3};"
        : "+f"(c[0]), "+f"(c[1]), "+f"(c[2]), "+f"(c[3])
        : "r"(a[0]), "r"(a[1]), "r"(a[2]), "r"(a[3]), "r"(b[0]), "r"(b[1]));
}
__device__ __forceinline__ void ldsm_x4(uint32_t* r, uint32_t addr)
{
    asm volatile("ldmatrix.sync.aligned.m8n8.x4.shared.b16 {%0,%1,%2,%3}, [%4];"
                 : "=r"(r[0]), "=r"(r[1]), "=r"(r[2]), "=r"(r[3]) : "r"(addr));
}
__device__ __forceinline__ void ldsm_x2(uint32_t* r, uint32_t addr)
{
    asm volatile("ldmatrix.sync.aligned.m8n8.x2.shared.b16 {%0,%1}, [%2];"
                 : "=r"(r[0]), "=r"(r[1]) : "r"(addr));
}

// ================= bf16-pair double-buffered mma GEMM =================
// C[M, N=grid.x*128] = (Ah+Al)[M,klen] @ (Bh+Bl)[N,klen]^T  (K-major bf16 pairs)
// flags: 1=+bias[n] 2=gelu 4=accum into C 8=/rowdiv[z*sdiv+m] 16=write bf16 pair (Ch,Cl)
// smem: 2 stages x 4 tiles x (128 rows x 80B pitch) = 81920 B dynamic
#define TILEB 10240
#define STG   (4*TILEB)
#define GSMEM (2*STG)

__global__ void __launch_bounds__(256) mma_gemm(
    const bf* __restrict__ Ah, const bf* __restrict__ Al,
    const bf* __restrict__ Bh, const bf* __restrict__ Bl,
    float* __restrict__ C, bf* __restrict__ Ch, bf* __restrict__ Cl,
    int M, int ldA, int ldB, int ldC,
    long long sA, long long sB, long long sC,
    int kstart, int kzs, int klen,
    const float* __restrict__ bias, const float* __restrict__ rowdiv, int sdiv, int flags)
{
    extern __shared__ __align__(16) char dsm[];
    uint32_t smb = smem_addr(dsm);

    int tid = threadIdx.x;
    int wid = tid >> 5, lane = tid & 31;
    int m0 = blockIdx.y * 128, n0 = blockIdx.x * 128, z = blockIdx.z;
    int warpM = wid >> 2;          // 0..1 -> 64 rows
    int warpN = wid & 3;           // 0..3 -> 32 cols
    int qr = lane >> 2;
    int qc = (lane & 3) * 2;

    const bf* Abh = Ah + (long long)z * sA + kstart + (long long)z * kzs;
    const bf* Abl = Al + (long long)z * sA + kstart + (long long)z * kzs;
    const bf* Bbh = Bh + (long long)z * sB + kstart + (long long)z * kzs;
    const bf* Bbl = Bl + (long long)z * sB + kstart + (long long)z * kzs;

    // load geometry: row = tid>>1, 32B chunk within 64B row slab
    int lrow = tid >> 1;
    int cb   = (tid & 1) * 16;                    // half offset
    int gm   = m0 + lrow;
    int gmc  = (gm < M) ? gm : (M - 1);
    int gn   = n0 + lrow;
    uint32_t so2 = (uint32_t)(lrow * 80 + cb * 2); // smem byte offset within tile

    // ldmatrix lane offsets (bytes, within a stage)
    uint32_t aoff = (uint32_t)((warpM * 64 + (lane & 15)) * 80 + ((lane >> 4) << 4));
    uint32_t boff = (uint32_t)((warpN * 32 + (lane & 7)) * 80 + (((lane >> 3) & 1) << 4));

    float acc[4][4][4];
#pragma unroll
    for (int i = 0; i < 4; i++)
#pragma unroll
        for (int j = 0; j < 4; j++)
#pragma unroll
            for (int r = 0; r < 4; r++) acc[i][j][r] = 0.f;

    int ktn = klen >> 5;

    uint4 rah[2], ral[2], rbh[2], rbl[2];
#define LOADREG(KT) do { \
    long long ko = ((long long)(KT) << 5) + cb; \
    const uint4* pa  = (const uint4*)(Abh + (long long)gmc * ldA + ko); \
    const uint4* pal = (const uint4*)(Abl + (long long)gmc * ldA + ko); \
    const uint4* pb  = (const uint4*)(Bbh + (long long)gn * ldB + ko); \
    const uint4* pbl = (const uint4*)(Bbl + (long long)gn * ldB + ko); \
    rah[0] = pa[0];  rah[1] = pa[1]; \
    ral[0] = pal[0]; ral[1] = pal[1]; \
    rbh[0] = pb[0];  rbh[1] = pb[1]; \
    rbl[0] = pbl[0]; rbl[1] = pbl[1]; \
} while (0)

#define STORE(SBASE) do { \
    char* p = dsm + (SBASE) + so2; \
    *(uint4*)(p)             = rah[0]; *(uint4*)(p + 16)             = rah[1]; \
    *(uint4*)(p + TILEB)     = ral[0]; *(uint4*)(p + TILEB + 16)     = ral[1]; \
    *(uint4*)(p + 2*TILEB)   = rbh[0]; *(uint4*)(p + 2*TILEB + 16)   = rbh[1]; \
    *(uint4*)(p + 3*TILEB)   = rbl[0]; *(uint4*)(p + 3*TILEB + 16)   = rbl[1]; \
} while (0)

    LOADREG(0);
    STORE(0);
    __syncthreads();

    for (int kt = 0; kt < ktn; kt++) {
        if (kt + 1 < ktn) LOADREG(kt + 1);
        uint32_t cur = smb + (uint32_t)(kt & 1) * STG;
        uint32_t AhS = cur, AlS = cur + TILEB, BhS = cur + 2 * TILEB, BlS = cur + 3 * TILEB;
#pragma unroll
        for (int ks = 0; ks < 2; ks++) {
            uint32_t kbyte = (uint32_t)(ks * 32);
            uint32_t bhf[4][2], blf[4][2];
#pragma unroll
            for (int nt = 0; nt < 4; nt++) {
                uint32_t bo = boff + (uint32_t)(nt * 8 * 80) + kbyte;
                ldsm_x2(bhf[nt], BhS + bo);
                ldsm_x2(blf[nt], BlS + bo);
            }
#pragma unroll
            for (int mt = 0; mt < 4; mt++) {
                uint32_t ao = aoff + (uint32_t)(mt * 16 * 80) + kbyte;
                uint32_t ahf[4], alf[4];
                ldsm_x4(ahf, AhS + ao);
                ldsm_x4(alf, AlS + ao);
#pragma unroll
                for (int nt = 0; nt < 4; nt++) {
                    mma_bf16(acc[mt][nt], ahf, bhf[nt]);
                    mma_bf16(acc[mt][nt], ahf, blf[nt]);
                    mma_bf16(acc[mt][nt], alf, bhf[nt]);
                }
            }
        }
        if (kt + 1 < ktn) STORE((uint32_t)((kt + 1) & 1) * STG);
        __syncthreads();
    }
#undef LOADREG
#undef STORE

    // ---- epilogue ----
#pragma unroll
    for (int mt = 0; mt < 4; mt++) {
        int r0 = m0 + warpM * 64 + mt * 16 + qr;
        int r1 = r0 + 8;
        bool ok0 = r0 < M, ok1 = r1 < M;
        float dv0 = 1.f, dv1 = 1.f;
        if (flags & 8) {
            if (ok0) dv0 = 1.f / rowdiv[(long long)z * sdiv + r0];
            if (ok1) dv1 = 1.f / rowdiv[(long long)z * sdiv + r1];
        }
#pragma unroll
        for (int nt = 0; nt < 4; nt++) {
            int col = n0 + warpN * 32 + nt * 8 + qc;
            float b0 = 0.f, b1 = 0.f;
            if (flags & 1) { b0 = bias[col]; b1 = bias[col + 1]; }
#pragma unroll
            for (int half = 0; half < 2; half++) {
                bool ok = half ? ok1 : ok0;
                if (!ok) continue;
                int r = half ? r1 : r0;
                long long base = (long long)z * sC + (long long)r * ldC + col;
                float v0 = acc[mt][nt][half * 2 + 0] + b0;
                float v1 = acc[mt][nt][half * 2 + 1] + b1;
                if (flags & 2) {
                    v0 = 0.5f * v0 * (1.f + erff(v0 * 0.70710678118654752f));
                    v1 = 0.5f * v1 * (1.f + erff(v1 * 0.70710678118654752f));
                }
                if (flags & 16) {
                    bf h0, l0, h1, l1;
                    bsplit(v0, h0, l0); bsplit(v1, h1, l1);
                    Ch[base] = h0; Ch[base + 1] = h1;
                    Cl[base] = l0; Cl[base + 1] = l1;
                } else {
                    float dv = half ? dv1 : dv0;
                    if (flags & 8) { v0 *= dv; v1 *= dv; }
                    if (flags & 4) { v0 += C[base]; v1 += C[base + 1]; }
                    C[base] = v0; C[base + 1] = v1;
                }
            }
        }
    }
}

// ================= fallback SGEMM (head only) =================
__global__ void __launch_bounds__(256) gemm_kernel(
    const float* __restrict__ A, const float* __restrict__ B, float* __restrict__ C,
    int M, int N, int K,
    const float* __restrict__ bias, int flags)
{
    __shared__ __align__(16) float As[8][128];
    __shared__ __align__(16) float Bs[8][128];
    int tid = threadIdx.x;
    int m0 = blockIdx.y * 128;
    int n0 = blockIdx.x * 128;
    int tx = tid & 15, ty = tid >> 4;
    float acc[8][8];
#pragma unroll
    for (int i = 0; i < 8; i++)
#pragma unroll
        for (int j = 0; j < 8; j++) acc[i][j] = 0.f;
    for (int k0 = 0; k0 < K; k0 += 8) {
#pragma unroll
        for (int i = 0; i < 4; i++) {
            int l = tid + i * 256;
            int mm = l >> 3, kk = l & 7;
            int gk = k0 + kk, gm = m0 + mm;
            As[kk][mm] = (gk < K && gm < M) ? A[(long long)gm * K + gk] : 0.f;
        }
#pragma unroll
        for (int i = 0; i < 4; i++) {
            int l = tid + i * 256;
            int kk = l >> 7, nn = l & 127;
            int gk = k0 + kk, gn = n0 + nn;
            Bs[kk][nn] = (gk < K && gn < N) ? B[(long long)gk * N + gn] : 0.f;
        }
        __syncthreads();
#pragma unroll
        for (int k = 0; k < 8; k++) {
            float4 a0 = *(const float4*)&As[k][ty * 4];
            float4 a1 = *(const float4*)&As[k][ty * 4 + 64];
            float4 b0 = *(const float4*)&Bs[k][tx * 4];
            float4 b1 = *(const float4*)&Bs[k][tx * 4 + 64];
            float af[8] = {a0.x, a0.y, a0.z, a0.w, a1.x, a1.y, a1.z, a1.w};
            float bf_[8] = {b0.x, b0.y, b0.z, b0.w, b1.x, b1.y, b1.z, b1.w};
#pragma unroll
            for (int i = 0; i < 8; i++)
#pragma unroll
                for (int j = 0; j < 8; j++) acc[i][j] += af[i] * bf_[j];
        }
        __syncthreads();
    }
#pragma unroll
    for (int i = 0; i < 8; i++) {
        int gm = m0 + ((i < 4) ? ty * 4 + i : 64 + ty * 4 + (i - 4));
        if (gm >= M) continue;
        float* crow = C + (long long)gm * N;
#pragma unroll
        for (int j = 0; j < 8; j++) {
            int gn = n0 + ((j < 4) ? tx * 4 + j : 64 + tx * 4 + (j - 4));
            if (gn >= N) continue;
            float v = acc[i][j];
            if (flags & 1) v += bias[gn];
            crow[gn] = v;
        }
    }
}

// ================= layernorm: warp per row; fp32 or bf16-pair output =================
__global__ void ln_kernel(const float* __restrict__ X, long long ldx,
                          float* __restrict__ Y, bf* __restrict__ Yh, bf* __restrict__ Yl,
                          long long ldy,
                          const float* __restrict__ g, const float* __restrict__ b,
                          float* __restrict__ diag, int nrows)
{
    int w = blockIdx.x * (blockDim.x >> 5) + (threadIdx.x >> 5);
    int lane = threadIdx.x & 31;
    if (w >= nrows) return;
    const float4* x = (const float4*)(X + (long long)w * ldx);
    float4 v[6];
    float s1 = 0.f, s2 = 0.f;
#pragma unroll
    for (int i = 0; i < 6; i++) {
        v[i] = x[lane + 32 * i];
        s1 += v[i].x + v[i].y + v[i].z + v[i].w;
        s2 += v[i].x * v[i].x + v[i].y * v[i].y + v[i].z * v[i].z + v[i].w * v[i].w;
    }
#pragma unroll
    for (int o = 16; o > 0; o >>= 1) {
        s1 += __shfl_xor_sync(0xffffffffu, s1, o);
        s2 += __shfl_xor_sync(0xffffffffu, s2, o);
    }
    float mu  = s1 * (1.0f / 768.0f);
    float var = s2 * (1.0f / 768.0f) - mu * mu;
    float inv = rsqrtf(var + 1e-5f);
    const float4* g4 = (const float4*)g;
    const float4* b4 = (const float4*)b;
    float d = 0.f;
#pragma unroll
    for (int i = 0; i < 6; i++) {
        float4 gv = g4[lane + 32 * i], bv = b4[lane + 32 * i], o;
        o.x = (v[i].x - mu) * inv * gv.x + bv.x;
        o.y = (v[i].y - mu) * inv * gv.y + bv.y;
        o.z = (v[i].z - mu) * inv * gv.z + bv.z;
        o.w = (v[i].w - mu) * inv * gv.w + bv.w;
        d += o.x * o.x + o.y * o.y + o.z * o.z + o.w * o.w;
        long long e = (long long)w * ldy + (lane + 32 * i) * 4;
        if (Yh) {
            bf h0, l0, h1, l1, h2, l2, h3, l3;
            bsplit(o.x, h0, l0); bsplit(o.y, h1, l1);
            bsplit(o.z, h2, l2); bsplit(o.w, h3, l3);
            __nv_bfloat162 ha = __halves2bfloat162(h0, h1);
            __nv_bfloat162 hb = __halves2bfloat162(h2, h3);
            __nv_bfloat162 la = __halves2bfloat162(l0, l1);
            __nv_bfloat162 lb = __halves2bfloat162(l2, l3);
            *(__nv_bfloat162*)&Yh[e] = ha; *(__nv_bfloat162*)&Yh[e + 2] = hb;
            *(__nv_bfloat162*)&Yl[e] = la; *(__nv_bfloat162*)&Yl[e + 2] = lb;
        } else {
            *(float4*)&Y[e] = o;
        }
    }
    if (diag) {
#pragma unroll
        for (int o = 16; o > 0; o >>= 1) d += __shfl_xor_sync(0xffffffffu, d, o);
        if (lane == 0) diag[w] = 0.5f * SCAL * SCAL * d;
    }
}

// ================= performer helpers =================
__global__ void lg_rowmax_kernel(float* __restrict__ lg, const float* __restrict__ diag,
                                 float* __restrict__ qmax)
{
    int row = blockIdx.x;
    int tid = threadIdx.x;
    long long idx = (long long)row * MFEAT + tid;
    float v = lg[idx] * SCAL - diag[row];
    lg[idx] = v;
    __shared__ float red[8];
    float m = v;
#pragma unroll
    for (int o = 16; o > 0; o >>= 1) m = fmaxf(m, __shfl_down_sync(0xffffffffu, m, o));
    int w = tid >> 5, lane = tid & 31;
    if (lane == 0) red[w] = m;
    __syncthreads();
    if (tid == 0) {
        float a = red[0];
        for (int i = 1; i < 8; i++) a = fmaxf(a, red[i]);
        qmax[row] = a;
    }
}

__global__ void gmax_kernel(const float* __restrict__ qmax, float* __restrict__ gmax)
{
    int tid = threadIdx.x;
    float m = -1e30f;
    for (int i = tid; i < ROWS; i += 256) m = fmaxf(m, qmax[i]);
    __shared__ float red[8];
#pragma unroll
    for (int o = 16; o > 0; o >>= 1) m = fmaxf(m, __shfl_down_sync(0xffffffffu, m, o));
    int w = tid >> 5, lane = tid & 31;
    if (lane == 0) red[w] = m;
    __syncthreads();
    if (tid == 0) {
        float a = red[0];
        for (int i = 1; i < 8; i++) a = fmaxf(a, red[i]);
        gmax[0] = a;
    }
}

__global__ void feat_kernel(const float* __restrict__ lg, const float* __restrict__ qmax,
                            const float* __restrict__ gmax,
                            bf* __restrict__ qfh, bf* __restrict__ qfl,
                            bf* __restrict__ kfTh, bf* __restrict__ kfTl)
{
    long long i = (long long)blockIdx.x * 256 + threadIdx.x;
    if (i >= (long long)ROWS * MFEAT) return;
    int tg = (int)(i >> 8);
    int m = (int)(i & 255);
    int b = tg / NTOK;
    int t = tg - b * NTOK;
    float v = lg[i];
    float q = expf(v - qmax[tg]) * MSCL + FEPS;
    float k = expf(v - gmax[0]) * MSCL + FEPS;
    bf h, l;
    bsplit(q, h, l); qfh[i] = h; qfl[i] = l;
    long long ki = ((long long)(b * MFEAT + m)) * KPAD + t;
    bsplit(k, h, l); kfTh[ki] = h; kfTl[ki] = l;
}

__global__ void ksum_kernel(const bf* __restrict__ kfTh, const bf* __restrict__ kfTl,
                            float* __restrict__ ksum)
{
    int w = (blockIdx.x * blockDim.x + threadIdx.x) >> 5;
    int lane = threadIdx.x & 31;
    if (w >= BSZ * MFEAT) return;
    const bf* ph = kfTh + (long long)w * KPAD;
    const bf* pl = kfTl + (long long)w * KPAD;
    float s = 0.f;
#pragma unroll
    for (int t = lane; t < KPAD; t += 32)
        s += __bfloat162float(ph[t]) + __bfloat162float(pl[t]);
#pragma unroll
    for (int o = 16; o > 0; o >>= 1) s += __shfl_down_sync(0xffffffffu, s, o);
    if (lane == 0) ksum[w] = s;
}

__global__ void den_kernel(const bf* __restrict__ qfh, const bf* __restrict__ qfl,
                           const float* __restrict__ ksum, float* __restrict__ den)
{
    int warp = (blockIdx.x * blockDim.x + threadIdx.x) >> 5;
    int lane = threadIdx.x & 31;
    if (warp >= ROWS) return;
    int b = warp / NTOK;
    const bf* qh = qfh + (long long)warp * MFEAT;
    const bf* ql = qfl + (long long)warp * MFEAT;
    const float* ks = ksum + b * MFEAT;
    float s = 0.f;
#pragma unroll
    for (int m = lane; m < MFEAT; m += 32)
        s += (__bfloat162float(qh[m]) + __bfloat162float(ql[m])) * ks[m];
#pragma unroll
    for (int o = 16; o > 0; o >>= 1) s += __shfl_down_sync(0xffffffffu, s, o);
    if (lane == 0) den[warp] = s;
}

// ================= transposes / converts =================
__global__ void transpose_pair(const bf* __restrict__ ih, const bf* __restrict__ il,
                               bf* __restrict__ oh, bf* __restrict__ ol,
                               int R, int Ccol, int ldo, long long sin, long long sout)
{
    __shared__ uint32_t t[32][33];
    const bf* iph = ih + (long long)blockIdx.z * sin;
    const bf* ipl = il + (long long)blockIdx.z * sin;
    bf* oph = oh + (long long)blockIdx.z * sout;
    bf* opl = ol + (long long)blockIdx.z * sout;
    int c0 = blockIdx.x * 32, r0 = blockIdx.y * 32;
    int tx = threadIdx.x, ty = threadIdx.y;
#pragma unroll
    for (int k = 0; k < 4; k++) {
        int r = r0 + ty + 8 * k;
        if (r < R && c0 + tx < Ccol) {
            long long idx = (long long)r * Ccol + c0 + tx;
            uint32_t hv = (uint32_t)*(const uint16_t*)&iph[idx];
            uint32_t lv = (uint32_t)*(const uint16_t*)&ipl[idx];
            t[ty + 8 * k][tx] = hv | (lv << 16);
        }
    }
    __syncthreads();
#pragma unroll
    for (int k = 0; k < 4; k++) {
        int c = c0 + ty + 8 * k;
        int r = r0 + tx;
        if (c < Ccol && r < R) {
            uint32_t v = t[tx][ty + 8 * k];
            long long idx = (long long)c * ldo + r;
            *(uint16_t*)&oph[idx] = (uint16_t)(v & 0xffff);
            *(uint16_t*)&opl[idx] = (uint16_t)(v >> 16);
        }
    }
}

__global__ void transpose_convert(const float* __restrict__ in,
                                  bf* __restrict__ oh, bf* __restrict__ ol,
                                  int R, int Ccol, long long sin, long long sout)
{
    __shared__ float t[32][33];
    const float* ip = in + (long long)blockIdx.z * sin;
    bf* oph = oh + (long long)blockIdx.z * sout;
    bf* opl = ol + (long long)blockIdx.z * sout;
    int c0 = blockIdx.x * 32, r0 = blockIdx.y * 32;
    int tx = threadIdx.x, ty = threadIdx.y;
#pragma unroll
    for (int k = 0; k < 4; k++) {
        int r = r0 + ty + 8 * k;
        if (r < R && c0 + tx < Ccol)
            t[ty + 8 * k][tx] = ip[(long long)r * Ccol + c0 + tx];
    }
    __syncthreads();
#pragma unroll
    for (int k = 0; k < 4; k++) {
        int c = c0 + ty + 8 * k;
        int r = r0 + tx;
        if (c < Ccol && r < R) {
            bf h, l;
            bsplit(t[tx][ty + 8 * k], h, l);
            long long idx = (long long)c * R + r;
            oph[idx] = h; opl[idx] = l;
        }
    }
}

__global__ void convert_pair(const float* __restrict__ in,
                             bf* __restrict__ oh, bf* __restrict__ ol, long long n)
{
    long long i = (long long)blockIdx.x * 256 + threadIdx.x;
    if (i >= n) return;
    bf h, l;
    bsplit(in[i], h, l);
    oh[i] = h; ol[i] = l;
}

// ================= misc elementwise =================
__global__ void im2col_kernel(const float* __restrict__ x,
                              bf* __restrict__ pth, bf* __restrict__ ptl)
{
    long long i = (long long)blockIdx.x * 256 + threadIdx.x;
    if (i >= (long long)BSZ * NPATCH * 768) return;
    int kidx = (int)(i % 768);
    int p    = (int)(i / 768);
    int pj = kidx & 15, pi = (kidx >> 4) & 15, c = kidx >> 8;
    int gj = p % 14;
    int t  = p / 14;
    int gi = t % 14;
    int b  = t / 14;
    float v = x[(((long long)(b * 3 + c) * 224 + gi * 16 + pi) * 224) + gj * 16 + pj];
    bf h, l;
    bsplit(v, h, l);
    pth[i] = h; ptl[i] = l;
}

__global__ void assemble_kernel(const float* __restrict__ tok, const float* __restrict__ cls_tok,
                                const float* __restrict__ pos, float* __restrict__ h)
{
    long long i = (long long)blockIdx.x * 256 + threadIdx.x;
    if (i >= (long long)ROWS * EDIM) return;
    int e = (int)(i % EDIM);
    int t = (int)(i / EDIM);
    int n = t % NTOK;
    int b = t / NTOK;
    float v = (n == 0) ? cls_tok[e] : tok[(long long)(b * NPATCH + n - 1) * EDIM + e];
    h[i] = v + pos[(long long)n * EDIM + e];
}

__global__ void combine_kernel(const float* __restrict__ part, const float* __restrict__ b2,
                               float* __restrict__ h)
{
    long long i = (long long)blockIdx.x * 256 + threadIdx.x;
    if (i >= (long long)ROWS * EDIM) return;
    int e = (int)(i % EDIM);
    h[i] += part[i] + part[(long long)ROWS * EDIM + i] + b2[e];
}

// ================= host =================
static inline void* symv(const void* s)
{
    void* p = nullptr;
    cudaGetSymbolAddress(&p, s);
    return p;
}

extern "C" void kernel_launch(void* const* d_in, const int* in_sizes, int n_in,
                              void* d_out, int out_size)
{
    const float* x       = (const float*)d_in[0];
    const float* cls_tok = (const float*)d_in[1];
    const float* pos_emb = (const float*)d_in[2];
    const float* patch_w = (const float*)d_in[3];
    const float* patch_b = (const float*)d_in[4];
    const float* ln1_g   = (const float*)d_in[5];
    const float* ln1_b   = (const float*)d_in[6];
    const float* proj    = (const float*)d_in[7];
    const float* ln2_g   = (const float*)d_in[8];
    const float* ln2_b   = (const float*)d_in[9];
    const float* w1      = (const float*)d_in[10];
    const float* b1      = (const float*)d_in[11];
    const float* w2      = (const float*)d_in[12];
    const float* b2      = (const float*)d_in[13];
    const float* lnf_g   = (const float*)d_in[14];
    const float* lnf_b   = (const float*)d_in[15];
    const float* head_w  = (const float*)d_in[16];
    const float* head_b  = (const float*)d_in[17];
    float* out = (float*)d_out;

    float* h    = (float*)symv(g_h);
    float* lg   = (float*)symv(g_lg);
    float* tok  = (float*)symv(g_tok);
    float* part = (float*)symv(g_part);
    float* diag = (float*)symv(g_diag);
    float* qmax = (float*)symv(g_qmax);
    float* den  = (float*)symv(g_den);
    float* ksum = (float*)symv(g_ksum);
    float* gmax = (float*)symv(g_gmax);
    float* clsb = (float*)symv(g_cls);

    bf* yh   = (bf*)symv(g_yh);   bf* yl   = (bf*)symv(g_yl);
    bf* qfh  = (bf*)symv(g_qfh);  bf* qfl  = (bf*)symv(g_qfl);
    bf* kfTh = (bf*)symv(g_kfTh); bf* kfTl = (bf*)symv(g_kfTl);
    bf* yTh  = (bf*)symv(g_yTh);  bf* yTl  = (bf*)symv(g_yTl);
    bf* kvTh = (bf*)symv(g_kvTh); bf* kvTl = (bf*)symv(g_kvTl);
    bf* tmph = (bf*)symv(g_tmph); bf* tmpl = (bf*)symv(g_tmpl);
    bf* pth  = (bf*)symv(g_pth);  bf* ptl  = (bf*)symv(g_ptl);
    bf* pwh  = (bf*)symv(g_pwh);  bf* pwl  = (bf*)symv(g_pwl);
    bf* pjh  = (bf*)symv(g_pjh);  bf* pjl  = (bf*)symv(g_pjl);
    bf* w1h  = (bf*)symv(g_w1h);  bf* w1l  = (bf*)symv(g_w1l);
    bf* w2h  = (bf*)symv(g_w2h);  bf* w2l  = (bf*)symv(g_w2l);

    cudaFuncSetAttribute(mma_gemm, cudaFuncAttributeMaxDynamicSharedMemorySize, GSMEM);

    // --- weight conversions ---
    {
        long long npw = (long long)EDIM * 768;
        convert_pair<<<(unsigned)((npw + 255) / 256), 256>>>(patch_w, pwh, pwl, npw);
        long long npj = (long long)NLAYER * MFEAT * EDIM;
        convert_pair<<<(unsigned)((npj + 255) / 256), 256>>>(proj, pjh, pjl, npj);
        dim3 blk(32, 8);
        // w1 [l][768][3072] -> [l][3072][768]
        transpose_convert<<<dim3(96, 24, NLAYER), blk>>>(w1, w1h, w1l,
            EDIM, FDIM, (long long)EDIM * FDIM, (long long)EDIM * FDIM);
        // w2 [l][3072][768] -> [l][768][3072]
        transpose_convert<<<dim3(24, 96, NLAYER), blk>>>(w2, w2h, w2l,
            FDIM, EDIM, (long long)EDIM * FDIM, (long long)EDIM * FDIM);
    }

    // --- patch embedding ---
    {
        long long tot = (long long)BSZ * NPATCH * 768;
        im2col_kernel<<<(unsigned)((tot + 255) / 256), 256>>>(x, pth, ptl);
        mma_gemm<<<dim3(6, 25, 1), 256, GSMEM>>>(pth, ptl, pwh, pwl,
            tok, nullptr, nullptr,
            BSZ * NPATCH, 768, 768, EDIM, 0, 0, 0, 0, 0, 768,
            patch_b, nullptr, 0, 1);
        long long ht = (long long)ROWS * EDIM;
        assemble_kernel<<<(unsigned)((ht + 255) / 256), 256>>>(tok, cls_tok, pos_emb, h);
    }

    for (int l = 0; l < NLAYER; l++) {
        long long pjo = (long long)l * MFEAT * EDIM;
        long long wo  = (long long)l * EDIM * FDIM;
        // LN1 -> y pair (+diag)
        ln_kernel<<<(ROWS + 7) / 8, 256>>>(h, EDIM, nullptr, yh, yl, EDIM,
            ln1_g + l * EDIM, ln1_b + l * EDIM, diag, ROWS);
        // logits = y @ proj^T -> lg fp32
        mma_gemm<<<dim3(2, 25, 1), 256, GSMEM>>>(yh, yl, pjh + pjo, pjl + pjo,
            lg, nullptr, nullptr,
            ROWS, EDIM, EDIM, MFEAT, 0, 0, 0, 0, 0, EDIM,
            nullptr, nullptr, 0, 0);
        lg_rowmax_kernel<<<ROWS, 256>>>(lg, diag, qmax);
        gmax_kernel<<<1, 256>>>(qmax, gmax);
        feat_kernel<<<(ROWS * MFEAT + 255) / 256, 256>>>(lg, qmax, gmax, qfh, qfl, kfTh, kfTl);
        ksum_kernel<<<(BSZ * MFEAT * 32 + 255) / 256, 256>>>(kfTh, kfTl, ksum);
        // yT pair
        transpose_pair<<<dim3(24, 7, BSZ), dim3(32, 8)>>>(yh, yl, yTh, yTl,
            NTOK, EDIM, KPAD, (long long)NTOK * EDIM, (long long)EDIM * KPAD);
        // kvT = yT @ kfT^T -> pair
        mma_gemm<<<dim3(2, 6, BSZ), 256, GSMEM>>>(yTh, yTl, kfTh, kfTl,
            nullptr, kvTh, kvTl,
            EDIM, KPAD, KPAD, MFEAT,
            (long long)EDIM * KPAD, (long long)MFEAT * KPAD, (long long)EDIM * MFEAT,
            0, 0, KPAD, nullptr, nullptr, 0, 16);
        den_kernel<<<(ROWS + 7) / 8, 256>>>(qfh, qfl, ksum, den);
        // h += (qf @ kvT^T) / den
        mma_gemm<<<dim3(6, 2, BSZ), 256, GSMEM>>>(qfh, qfl, kvTh, kvTl,
            h, nullptr, nullptr,
            NTOK, MFEAT, MFEAT, EDIM,
            (long long)NTOK * MFEAT, (long long)EDIM * MFEAT, (long long)NTOK * EDIM,
            0, 0, MFEAT, nullptr, den, NTOK, 4 | 8);
        // LN2 -> y pair
        ln_kernel<<<(ROWS + 7) / 8, 256>>>(h, EDIM, nullptr, yh, yl, EDIM,
            ln2_g + l * EDIM, ln2_b + l * EDIM, nullptr, ROWS);
        // hid = gelu(y @ w1 + b1) -> tmp pair
        mma_gemm<<<dim3(24, 25, 1), 256, GSMEM>>>(yh, yl, w1h + wo, w1l + wo,
            nullptr, tmph, tmpl,
            ROWS, EDIM, EDIM, FDIM, 0, 0, 0, 0, 0, EDIM,
            b1 + l * FDIM, nullptr, 0, 1 | 2 | 16);
        // part[z] = hid[:, z*1536:] @ w2T[:, z*1536:]^T (split-K over 2)
        mma_gemm<<<dim3(6, 25, 2), 256, GSMEM>>>(tmph, tmpl, w2h + wo, w2l + wo,
            part, nullptr, nullptr,
            ROWS, FDIM, FDIM, EDIM, 0, 0, (long long)ROWS * EDIM,
            0, FDIM / 2, FDIM / 2, nullptr, nullptr, 0, 0);
        combine_kernel<<<(ROWS * EDIM + 255) / 256, 256>>>(part, b2 + l * EDIM, h);
    }

    // final LN on CLS tokens + head
    ln_kernel<<<2, 256>>>(h, (long long)NTOK * EDIM, clsb, nullptr, nullptr, EDIM,
        lnf_g, lnf_b, nullptr, BSZ);
    {
        dim3 grid(8, 1, 1);
        gemm_kernel<<<grid, 256>>>(clsb, head_w, out,
            BSZ, NC, EDIM, head_b, 1);
    }
}

// round 13
// speedup vs baseline: 1.4854x; 1.0396x over previous
#include <cuda_runtime.h>
#include <cuda_bf16.h>
#include <math.h>
#include <stdint.h>

// ---------------- problem constants ----------------
#define EDIM   768
#define NTOK   197
#define BSZ    16
#define ROWS   (BSZ*NTOK)      // 3152
#define MFEAT  256
#define FDIM   3072
#define NPATCH 196
#define NC     1000
#define NLAYER 12
#define KPAD   224             // 197 padded to mult of 32

#define SCAL  0.18995897f      // 768^{-1/4}
#define MSCL  0.0625f          // 256^{-1/2}
#define FEPS  1e-4f

typedef __nv_bfloat16 bf;

// ---------------- scratch (device globals; allocation-free) ----------------
__device__ float g_h   [ROWS*EDIM];
__device__ float g_y   [ROWS*EDIM];
__device__ float g_tmp [ROWS*FDIM];          // MLP hidden; im2col+tok at start
__device__ float g_lg  [ROWS*MFEAT];
__device__ float g_qf  [ROWS*MFEAT];
__device__ float g_yT  [BSZ*EDIM*KPAD];      // fp32, zero-padded t>=197
__device__ float g_part[2*ROWS*EDIM];
__device__ float g_diag[ROWS];
__device__ float g_qmax[ROWS];
__device__ float g_den [ROWS];
__device__ float g_ksum[BSZ*MFEAT];
__device__ float g_gmax[1];
__device__ float g_cls [BSZ*EDIM];

// bf16 hi/lo pairs (B-side operands only)
__device__ bf g_kfTh[BSZ*MFEAT*KPAD], g_kfTl[BSZ*MFEAT*KPAD];
__device__ bf g_kvTh[BSZ*EDIM*MFEAT], g_kvTl[BSZ*EDIM*MFEAT];
__device__ bf g_pwh [EDIM*768],       g_pwl [EDIM*768];
__device__ bf g_pjh [NLAYER*MFEAT*EDIM], g_pjl [NLAYER*MFEAT*EDIM];
__device__ bf g_w1h [NLAYER*FDIM*EDIM],  g_w1l [NLAYER*FDIM*EDIM];
__device__ bf g_w2h [NLAYER*EDIM*FDIM],  g_w2l [NLAYER*EDIM*FDIM];

// ---------------- helpers ----------------
__device__ __forceinline__ void bsplit(float v, bf& h, bf& l)
{
    h = __float2bfloat16(v);
    l = __float2bfloat16(v - __bfloat162float(h));
}

__device__ __forceinline__ uint32_t smem_addr(const void* p)
{
    uint32_t a;
    asm("{ .reg .u64 t; cvta.to.shared.u64 t, %1; cvt.u32.u64 %0, t; }"
        : "=r"(a) : "l"(p));
    return a;
}

__device__ __forceinline__ void mma_bf16(float* c, const uint32_t* a, const uint32_t* b)
{
    asm volatile(
        "mma.sync.aligned.m16n8k16.row.col.f32.bf16.bf16.f32 "
        "{%0,%1,%2,%3}, {%4,%5,%6,%7}, {%8,%9}, {%0,%1,%2,%3};"
        : "+f"(c[0]), "+f"(c[1]), "+f"(c[2]), "+f"(c[3])
        : "r"(a[0]), "r"(a[1]), "r"(a[2]), "r"(a[3]), "r"(b[0]), "r"(b[1]));
}
__device__ __forceinline__ void ldsm_x4(uint32_t* r, uint32_t addr)
{
    asm volatile("ldmatrix.sync.aligned.m8n8.x4.shared.b16 {%0,%1,%2,%3}, [%4];"
                 : "=r"(r[0]), "=r"(r[1]), "=r"(r[2]), "=r"(r[3]) : "r"(addr));
}
__device__ __forceinline__ void ldsm_x2(uint32_t* r, uint32_t addr)
{
    asm volatile("ldmatrix.sync.aligned.m8n8.x2.shared.b16 {%0,%1}, [%2];"
                 : "=r"(r[0]), "=r"(r[1]) : "r"(addr));
}

// split float4 -> packed hi(2xuint) and lo(2xuint) bf16x2
__device__ __forceinline__ void split_pack(float4 v, uint2& hi, uint2& lo)
{
    bf hx = __float2bfloat16(v.x);
    bf hy = __float2bfloat16(v.y);
    bf hz = __float2bfloat16(v.z);
    bf hw = __float2bfloat16(v.w);
    bf lx = __float2bfloat16(v.x - __bfloat162float(hx));
    bf ly = __float2bfloat16(v.y - __bfloat162float(hy));
    bf lz = __float2bfloat16(v.z - __bfloat162float(hz));
    bf lw = __float2bfloat16(v.w - __bfloat162float(hw));
    __nv_bfloat162 h0 = __halves2bfloat162(hx, hy);
    __nv_bfloat162 h1 = __halves2bfloat162(hz, hw);
    __nv_bfloat162 l0 = __halves2bfloat162(lx, ly);
    __nv_bfloat162 l1 = __halves2bfloat162(lz, lw);
    hi.x = *(uint32_t*)&h0; hi.y = *(uint32_t*)&h1;
    lo.x = *(uint32_t*)&l0; lo.y = *(uint32_t*)&l1;
}

// ================= hybrid mma GEMM =================
// C[M, N=grid.x*128] = A[M,klen](fp32) @ (Bh+Bl)[N,klen]^T (bf16 pair), K-major.
// A split to bf16 pair in-kernel; B pre-split. 3-product bf16 split accumulate.
// flags: 1=+bias[n] 2=gelu 4=accum into C 8=/rowdiv[z*sdiv+m] 16=write bf16 pair (Ch,Cl)
#define TILEB 10240            // 128 rows x 80B pitch
#define STG   (4*TILEB)        // Ah,Al,Bh,Bl
#define GSMEM (2*STG)          // 81920 (double-buffered)

__global__ void __launch_bounds__(256) mma_gemm(
    const float* __restrict__ A,
    const bf* __restrict__ Bh, const bf* __restrict__ Bl,
    float* __restrict__ C, bf* __restrict__ Ch, bf* __restrict__ Cl,
    int M, int ldA, int ldB, int ldC,
    long long sA, long long sB, long long sC,
    int kstart, int kzs, int klen,
    const float* __restrict__ bias, const float* __restrict__ rowdiv, int sdiv, int flags)
{
    extern __shared__ __align__(16) char dsm[];
    uint32_t smb = smem_addr(dsm);

    int tid = threadIdx.x;
    int wid = tid >> 5, lane = tid & 31;
    int m0 = blockIdx.y * 128, n0 = blockIdx.x * 128, z = blockIdx.z;
    int warpM = wid >> 2;          // 0..1 -> 64 rows
    int warpN = wid & 3;           // 0..3 -> 32 cols
    int qr = lane >> 2;
    int qc = (lane & 3) * 2;

    const float* Ab = A + (long long)z * sA + kstart + (long long)z * kzs;
    const bf* Bbh = Bh + (long long)z * sB + kstart + (long long)z * kzs;
    const bf* Bbl = Bl + (long long)z * sB + kstart + (long long)z * kzs;

    // load geometry: row = tid>>1, element chunk (tid&1)*16 within 32-elem K-tile row
    int lrow = tid >> 1;
    int ce   = (tid & 1) * 16;
    int gm   = m0 + lrow;
    int gmc  = (gm < M) ? gm : (M - 1);
    int gn   = n0 + lrow;
    uint32_t sob = (uint32_t)((lrow * 40 + ce) * 2);   // byte offset within tile

    // ldmatrix lane offsets (bytes, within a stage)
    uint32_t aoff = (uint32_t)((warpM * 64 + (lane & 15)) * 80 + ((lane >> 4) << 4));
    uint32_t boff = (uint32_t)((warpN * 32 + (lane & 7)) * 80 + (((lane >> 3) & 1) << 4));

    float acc[4][4][4];
#pragma unroll
    for (int i = 0; i < 4; i++)
#pragma unroll
        for (int j = 0; j < 4; j++)
#pragma unroll
            for (int r = 0; r < 4; r++) acc[i][j][r] = 0.f;

    int ktn = klen >> 5;

    float4 av[4];
    uint4 bu[4];
#define LOADREG(KT) do { \
    long long ko = ((long long)(KT) << 5) + ce; \
    const float4* pa = (const float4*)(Ab + (long long)gmc * ldA + ko); \
    av[0] = pa[0]; av[1] = pa[1]; av[2] = pa[2]; av[3] = pa[3]; \
    const uint4* pbh = (const uint4*)(Bbh + (long long)gn * ldB + ko); \
    bu[0] = pbh[0]; bu[1] = pbh[1]; \
    const uint4* pbl = (const uint4*)(Bbl + (long long)gn * ldB + ko); \
    bu[2] = pbl[0]; bu[3] = pbl[1]; \
} while (0)

#define CONVSTORE(SB) do { \
    char* p = dsm + (SB) + sob; \
    uint2 hi, lo; \
    split_pack(av[0], hi, lo); *(uint2*)(p)      = hi; *(uint2*)(p + TILEB)      = lo; \
    split_pack(av[1], hi, lo); *(uint2*)(p + 8)  = hi; *(uint2*)(p + TILEB + 8)  = lo; \
    split_pack(av[2], hi, lo); *(uint2*)(p + 16) = hi; *(uint2*)(p + TILEB + 16) = lo; \
    split_pack(av[3], hi, lo); *(uint2*)(p + 24) = hi; *(uint2*)(p + TILEB + 24) = lo; \
    *(uint4*)(p + 2*TILEB)      = bu[0]; *(uint4*)(p + 2*TILEB + 16) = bu[1]; \
    *(uint4*)(p + 3*TILEB)      = bu[2]; *(uint4*)(p + 3*TILEB + 16) = bu[3]; \
} while (0)

    LOADREG(0);
    CONVSTORE(0);
    __syncthreads();

    for (int kt = 0; kt < ktn; kt++) {
        if (kt + 1 < ktn) LOADREG(kt + 1);
        uint32_t cur = smb + (uint32_t)(kt & 1) * STG;
        uint32_t AhS = cur, AlS = cur + TILEB, BhS = cur + 2 * TILEB, BlS = cur + 3 * TILEB;
#pragma unroll
        for (int ks = 0; ks < 2; ks++) {
            uint32_t kbyte = (uint32_t)(ks * 32);
            uint32_t bhf[4][2], blf[4][2];
#pragma unroll
            for (int nt = 0; nt < 4; nt++) {
                uint32_t bo = boff + (uint32_t)(nt * 8 * 80) + kbyte;
                ldsm_x2(bhf[nt], BhS + bo);
                ldsm_x2(blf[nt], BlS + bo);
            }
#pragma unroll
            for (int mt = 0; mt < 4; mt++) {
                uint32_t ao = aoff + (uint32_t)(mt * 16 * 80) + kbyte;
                uint32_t ahf[4], alf[4];
                ldsm_x4(ahf, AhS + ao);
                ldsm_x4(alf, AlS + ao);
#pragma unroll
                for (int nt = 0; nt < 4; nt++) {
                    mma_bf16(acc[mt][nt], ahf, bhf[nt]);
                    mma_bf16(acc[mt][nt], ahf, blf[nt]);
                    mma_bf16(acc[mt][nt], alf, bhf[nt]);
                }
            }
        }
        if (kt + 1 < ktn) CONVSTORE((uint32_t)((kt + 1) & 1) * STG);
        __syncthreads();
    }
#undef LOADREG
#undef CONVSTORE

    // ---- epilogue ----
#pragma unroll
    for (int mt = 0; mt < 4; mt++) {
        int r0 = m0 + warpM * 64 + mt * 16 + qr;
        int r1 = r0 + 8;
        bool ok0 = r0 < M, ok1 = r1 < M;
        float dv0 = 1.f, dv1 = 1.f;
        if (flags & 8) {
            if (ok0) dv0 = 1.f / rowdiv[(long long)z * sdiv + r0];
            if (ok1) dv1 = 1.f / rowdiv[(long long)z * sdiv + r1];
        }
#pragma unroll
        for (int nt = 0; nt < 4; nt++) {
            int col = n0 + warpN * 32 + nt * 8 + qc;
            float b0 = 0.f, b1 = 0.f;
            if (flags & 1) { b0 = bias[col]; b1 = bias[col + 1]; }
#pragma unroll
            for (int half = 0; half < 2; half++) {
                bool ok = half ? ok1 : ok0;
                if (!ok) continue;
                int r = half ? r1 : r0;
                long long base = (long long)z * sC + (long long)r * ldC + col;
                float v0 = acc[mt][nt][half * 2 + 0] + b0;
                float v1 = acc[mt][nt][half * 2 + 1] + b1;
                if (flags & 2) {
                    v0 = 0.5f * v0 * (1.f + erff(v0 * 0.70710678118654752f));
                    v1 = 0.5f * v1 * (1.f + erff(v1 * 0.70710678118654752f));
                }
                if (flags & 16) {
                    bf h0, l0, h1, l1;
                    bsplit(v0, h0, l0); bsplit(v1, h1, l1);
                    Ch[base] = h0; Ch[base + 1] = h1;
                    Cl[base] = l0; Cl[base + 1] = l1;
                } else {
                    float dv = half ? dv1 : dv0;
                    if (flags & 8) { v0 *= dv; v1 *= dv; }
                    if (flags & 4) { v0 += C[base]; v1 += C[base + 1]; }
                    C[base] = v0; C[base + 1] = v1;
                }
            }
        }
    }
}

// ================= fallback SGEMM (head only) =================
__global__ void __launch_bounds__(256) gemm_kernel(
    const float* __restrict__ A, const float* __restrict__ B, float* __restrict__ C,
    int M, int N, int K,
    const float* __restrict__ bias, int flags)
{
    __shared__ __align__(16) float As[8][128];
    __shared__ __align__(16) float Bs[8][128];
    int tid = threadIdx.x;
    int m0 = blockIdx.y * 128;
    int n0 = blockIdx.x * 128;
    int tx = tid & 15, ty = tid >> 4;
    float acc[8][8];
#pragma unroll
    for (int i = 0; i < 8; i++)
#pragma unroll
        for (int j = 0; j < 8; j++) acc[i][j] = 0.f;
    for (int k0 = 0; k0 < K; k0 += 8) {
#pragma unroll
        for (int i = 0; i < 4; i++) {
            int l = tid + i * 256;
            int mm = l >> 3, kk = l & 7;
            int gk = k0 + kk, gm = m0 + mm;
            As[kk][mm] = (gk < K && gm < M) ? A[(long long)gm * K + gk] : 0.f;
        }
#pragma unroll
        for (int i = 0; i < 4; i++) {
            int l = tid + i * 256;
            int kk = l >> 7, nn = l & 127;
            int gk = k0 + kk, gn = n0 + nn;
            Bs[kk][nn] = (gk < K && gn < N) ? B[(long long)gk * N + gn] : 0.f;
        }
        __syncthreads();
#pragma unroll
        for (int k = 0; k < 8; k++) {
            float4 a0 = *(const float4*)&As[k][ty * 4];
            float4 a1 = *(const float4*)&As[k][ty * 4 + 64];
            float4 b0 = *(const float4*)&Bs[k][tx * 4];
            float4 b1 = *(const float4*)&Bs[k][tx * 4 + 64];
            float af[8] = {a0.x, a0.y, a0.z, a0.w, a1.x, a1.y, a1.z, a1.w};
            float bf_[8] = {b0.x, b0.y, b0.z, b0.w, b1.x, b1.y, b1.z, b1.w};
#pragma unroll
            for (int i = 0; i < 8; i++)
#pragma unroll
                for (int j = 0; j < 8; j++) acc[i][j] += af[i] * bf_[j];
        }
        __syncthreads();
    }
#pragma unroll
    for (int i = 0; i < 8; i++) {
        int gm = m0 + ((i < 4) ? ty * 4 + i : 64 + ty * 4 + (i - 4));
        if (gm >= M) continue;
        float* crow = C + (long long)gm * N;
#pragma unroll
        for (int j = 0; j < 8; j++) {
            int gn = n0 + ((j < 4) ? tx * 4 + j : 64 + tx * 4 + (j - 4));
            if (gn >= N) continue;
            float v = acc[i][j];
            if (flags & 1) v += bias[gn];
            crow[gn] = v;
        }
    }
}

// ================= layernorm: warp per row, fp32 out =================
__global__ void ln_kernel(const float* __restrict__ X, long long ldx,
                          float* __restrict__ Y, long long ldy,
                          const float* __restrict__ g, const float* __restrict__ b,
                          float* __restrict__ diag, int nrows)
{
    int w = blockIdx.x * (blockDim.x >> 5) + (threadIdx.x >> 5);
    int lane = threadIdx.x & 31;
    if (w >= nrows) return;
    const float4* x = (const float4*)(X + (long long)w * ldx);
    float4 v[6];
    float s1 = 0.f, s2 = 0.f;
#pragma unroll
    for (int i = 0; i < 6; i++) {
        v[i] = x[lane + 32 * i];
        s1 += v[i].x + v[i].y + v[i].z + v[i].w;
        s2 += v[i].x * v[i].x + v[i].y * v[i].y + v[i].z * v[i].z + v[i].w * v[i].w;
    }
#pragma unroll
    for (int o = 16; o > 0; o >>= 1) {
        s1 += __shfl_xor_sync(0xffffffffu, s1, o);
        s2 += __shfl_xor_sync(0xffffffffu, s2, o);
    }
    float mu  = s1 * (1.0f / 768.0f);
    float var = s2 * (1.0f / 768.0f) - mu * mu;
    float inv = rsqrtf(var + 1e-5f);
    const float4* g4 = (const float4*)g;
    const float4* b4 = (const float4*)b;
    float4* y4 = (float4*)(Y + (long long)w * ldy);
    float d = 0.f;
#pragma unroll
    for (int i = 0; i < 6; i++) {
        float4 gv = g4[lane + 32 * i], bv = b4[lane + 32 * i], o;
        o.x = (v[i].x - mu) * inv * gv.x + bv.x;
        o.y = (v[i].y - mu) * inv * gv.y + bv.y;
        o.z = (v[i].z - mu) * inv * gv.z + bv.z;
        o.w = (v[i].w - mu) * inv * gv.w + bv.w;
        d += o.x * o.x + o.y * o.y + o.z * o.z + o.w * o.w;
        y4[lane + 32 * i] = o;
    }
    if (diag) {
#pragma unroll
        for (int o = 16; o > 0; o >>= 1) d += __shfl_xor_sync(0xffffffffu, d, o);
        if (lane == 0) diag[w] = 0.5f * SCAL * SCAL * d;
    }
}

// ================= performer helpers =================
__global__ void lg_rowmax_kernel(float* __restrict__ lg, const float* __restrict__ diag,
                                 float* __restrict__ qmax)
{
    int row = blockIdx.x;
    int tid = threadIdx.x;
    long long idx = (long long)row * MFEAT + tid;
    float v = lg[idx] * SCAL - diag[row];
    lg[idx] = v;
    __shared__ float red[8];
    float m = v;
#pragma unroll
    for (int o = 16; o > 0; o >>= 1) m = fmaxf(m, __shfl_down_sync(0xffffffffu, m, o));
    int w = tid >> 5, lane = tid & 31;
    if (lane == 0) red[w] = m;
    __syncthreads();
    if (tid == 0) {
        float a = red[0];
        for (int i = 1; i < 8; i++) a = fmaxf(a, red[i]);
        qmax[row] = a;
    }
}

__global__ void gmax_kernel(const float* __restrict__ qmax, float* __restrict__ gmax)
{
    int tid = threadIdx.x;
    float m = -1e30f;
    for (int i = tid; i < ROWS; i += 256) m = fmaxf(m, qmax[i]);
    __shared__ float red[8];
#pragma unroll
    for (int o = 16; o > 0; o >>= 1) m = fmaxf(m, __shfl_down_sync(0xffffffffu, m, o));
    int w = tid >> 5, lane = tid & 31;
    if (lane == 0) red[w] = m;
    __syncthreads();
    if (tid == 0) {
        float a = red[0];
        for (int i = 1; i < 8; i++) a = fmaxf(a, red[i]);
        gmax[0] = a;
    }
}

// qf fp32 (A-side); kfT bf16 pair (B-side)
__global__ void feat_kernel(const float* __restrict__ lg, const float* __restrict__ qmax,
                            const float* __restrict__ gmax,
                            float* __restrict__ qf,
                            bf* __restrict__ kfTh, bf* __restrict__ kfTl)
{
    long long i = (long long)blockIdx.x * 256 + threadIdx.x;
    if (i >= (long long)ROWS * MFEAT) return;
    int tg = (int)(i >> 8);
    int m = (int)(i & 255);
    int b = tg / NTOK;
    int t = tg - b * NTOK;
    float v = lg[i];
    qf[i] = expf(v - qmax[tg]) * MSCL + FEPS;
    float k = expf(v - gmax[0]) * MSCL + FEPS;
    long long ki = ((long long)(b * MFEAT + m)) * KPAD + t;
    bf h, l;
    bsplit(k, h, l);
    kfTh[ki] = h; kfTl[ki] = l;
}

__global__ void ksum_kernel(const bf* __restrict__ kfTh, const bf* __restrict__ kfTl,
                            float* __restrict__ ksum)
{
    int w = (blockIdx.x * blockDim.x + threadIdx.x) >> 5;
    int lane = threadIdx.x & 31;
    if (w >= BSZ * MFEAT) return;
    const bf* ph = kfTh + (long long)w * KPAD;
    const bf* pl = kfTl + (long long)w * KPAD;
    float s = 0.f;
#pragma unroll
    for (int t = lane; t < KPAD; t += 32)
        s += __bfloat162float(ph[t]) + __bfloat162float(pl[t]);
#pragma unroll
    for (int o = 16; o > 0; o >>= 1) s += __shfl_down_sync(0xffffffffu, s, o);
    if (lane == 0) ksum[w] = s;
}

__global__ void den_kernel(const float* __restrict__ qf, const float* __restrict__ ksum,
                           float* __restrict__ den)
{
    int warp = (blockIdx.x * blockDim.x + threadIdx.x) >> 5;
    int lane = threadIdx.x & 31;
    if (warp >= ROWS) return;
    int b = warp / NTOK;
    const float* q  = qf + (long long)warp * MFEAT;
    const float* ks = ksum + b * MFEAT;
    float s = 0.f;
#pragma unroll
    for (int m = lane; m < MFEAT; m += 32) s += q[m] * ks[m];
#pragma unroll
    for (int o = 16; o > 0; o >>= 1) s += __shfl_down_sync(0xffffffffu, s, o);
    if (lane == 0) den[warp] = s;
}

// ================= transposes / converts =================
// fp32 transpose: out[c][r] = in[r][c], out row stride ldo, per z
__global__ void transpose_tiled(const float* __restrict__ in, float* __restrict__ out,
                                int R, int Ccol, int ldo, long long sin, long long sout)
{
    __shared__ float t[32][33];
    const float* ip = in + (long long)blockIdx.z * sin;
    float* op = out + (long long)blockIdx.z * sout;
    int c0 = blockIdx.x * 32, r0 = blockIdx.y * 32;
    int tx = threadIdx.x, ty = threadIdx.y;
#pragma unroll
    for (int k = 0; k < 4; k++) {
        int r = r0 + ty + 8 * k;
        if (r < R && c0 + tx < Ccol)
            t[ty + 8 * k][tx] = ip[(long long)r * Ccol + c0 + tx];
    }
    __syncthreads();
#pragma unroll
    for (int k = 0; k < 4; k++) {
        int c = c0 + ty + 8 * k;
        int r = r0 + tx;
        if (c < Ccol && r < R)
            op[(long long)c * ldo + r] = t[tx][ty + 8 * k];
    }
}

// transpose+convert fp32 [z][R][C] -> bf16 pair [z][C][R]
__global__ void transpose_convert(const float* __restrict__ in,
                                  bf* __restrict__ oh, bf* __restrict__ ol,
                                  int R, int Ccol, long long sin, long long sout)
{
    __shared__ float t[32][33];
    const float* ip = in + (long long)blockIdx.z * sin;
    bf* oph = oh + (long long)blockIdx.z * sout;
    bf* opl = ol + (long long)blockIdx.z * sout;
    int c0 = blockIdx.x * 32, r0 = blockIdx.y * 32;
    int tx = threadIdx.x, ty = threadIdx.y;
#pragma unroll
    for (int k = 0; k < 4; k++) {
        int r = r0 + ty + 8 * k;
        if (r < R && c0 + tx < Ccol)
            t[ty + 8 * k][tx] = ip[(long long)r * Ccol + c0 + tx];
    }
    __syncthreads();
#pragma unroll
    for (int k = 0; k < 4; k++) {
        int c = c0 + ty + 8 * k;
        int r = r0 + tx;
        if (c < Ccol && r < R) {
            bf h, l;
            bsplit(t[tx][ty + 8 * k], h, l);
            long long idx = (long long)c * R + r;
            oph[idx] = h; opl[idx] = l;
        }
    }
}

__global__ void convert_pair(const float* __restrict__ in,
                             bf* __restrict__ oh, bf* __restrict__ ol, long long n)
{
    long long i = (long long)blockIdx.x * 256 + threadIdx.x;
    if (i >= n) return;
    bf h, l;
    bsplit(in[i], h, l);
    oh[i] = h; ol[i] = l;
}

// ================= misc elementwise =================
__global__ void im2col_kernel(const float* __restrict__ x, float* __restrict__ pt)
{
    long long i = (long long)blockIdx.x * 256 + threadIdx.x;
    if (i >= (long long)BSZ * NPATCH * 768) return;
    int kidx = (int)(i % 768);
    int p    = (int)(i / 768);
    int pj = kidx & 15, pi = (kidx >> 4) & 15, c = kidx >> 8;
    int gj = p % 14;
    int t  = p / 14;
    int gi = t % 14;
    int b  = t / 14;
    pt[i] = x[(((long long)(b * 3 + c) * 224 + gi * 16 + pi) * 224) + gj * 16 + pj];
}

__global__ void assemble_kernel(const float* __restrict__ tok, const float* __restrict__ cls_tok,
                                const float* __restrict__ pos, float* __restrict__ h)
{
    long long i = (long long)blockIdx.x * 256 + threadIdx.x;
    if (i >= (long long)ROWS * EDIM) return;
    int e = (int)(i % EDIM);
    int t = (int)(i / EDIM);
    int n = t % NTOK;
    int b = t / NTOK;
    float v = (n == 0) ? cls_tok[e] : tok[(long long)(b * NPATCH + n - 1) * EDIM + e];
    h[i] = v + pos[(long long)n * EDIM + e];
}

__global__ void combine_kernel(const float* __restrict__ part, const float* __restrict__ b2,
                               float* __restrict__ h)
{
    long long i = (long long)blockIdx.x * 256 + threadIdx.x;
    if (i >= (long long)ROWS * EDIM) return;
    int e = (int)(i % EDIM);
    h[i] += part[i] + part[(long long)ROWS * EDIM + i] + b2[e];
}

// ================= host =================
static inline void* symv(const void* s)
{
    void* p = nullptr;
    cudaGetSymbolAddress(&p, s);
    return p;
}

extern "C" void kernel_launch(void* const* d_in, const int* in_sizes, int n_in,
                              void* d_out, int out_size)
{
    const float* x       = (const float*)d_in[0];
    const float* cls_tok = (const float*)d_in[1];
    const float* pos_emb = (const float*)d_in[2];
    const float* patch_w = (const float*)d_in[3];
    const float* patch_b = (const float*)d_in[4];
    const float* ln1_g   = (const float*)d_in[5];
    const float* ln1_b   = (const float*)d_in[6];
    const float* proj    = (const float*)d_in[7];
    const float* ln2_g   = (const float*)d_in[8];
    const float* ln2_b   = (const float*)d_in[9];
    const float* w1      = (const float*)d_in[10];
    const float* b1      = (const float*)d_in[11];
    const float* w2      = (const float*)d_in[12];
    const float* b2      = (const float*)d_in[13];
    const float* lnf_g   = (const float*)d_in[14];
    const float* lnf_b   = (const float*)d_in[15];
    const float* head_w  = (const float*)d_in[16];
    const float* head_b  = (const float*)d_in[17];
    float* out = (float*)d_out;

    float* h    = (float*)symv(g_h);
    float* y    = (float*)symv(g_y);
    float* tmp  = (float*)symv(g_tmp);
    float* lg   = (float*)symv(g_lg);
    float* qf   = (float*)symv(g_qf);
    float* yT   = (float*)symv(g_yT);
    float* part = (float*)symv(g_part);
    float* diag = (float*)symv(g_diag);
    float* qmax = (float*)symv(g_qmax);
    float* den  = (float*)symv(g_den);
    float* ksum = (float*)symv(g_ksum);
    float* gmax = (float*)symv(g_gmax);
    float* clsb = (float*)symv(g_cls);

    bf* kfTh = (bf*)symv(g_kfTh); bf* kfTl = (bf*)symv(g_kfTl);
    bf* kvTh = (bf*)symv(g_kvTh); bf* kvTl = (bf*)symv(g_kvTl);
    bf* pwh  = (bf*)symv(g_pwh);  bf* pwl  = (bf*)symv(g_pwl);
    bf* pjh  = (bf*)symv(g_pjh);  bf* pjl  = (bf*)symv(g_pjl);
    bf* w1h  = (bf*)symv(g_w1h);  bf* w1l  = (bf*)symv(g_w1l);
    bf* w2h  = (bf*)symv(g_w2h);  bf* w2l  = (bf*)symv(g_w2l);

    cudaFuncSetAttribute(mma_gemm, cudaFuncAttributeMaxDynamicSharedMemorySize, GSMEM);

    float* pt  = tmp;             // [3136,768] im2col
    float* tok = tmp + 5000000;   // [3136,768] patch-embed out

    // --- weight conversions (pre-split B operands) ---
    {
        long long npw = (long long)EDIM * 768;
        convert_pair<<<(unsigned)((npw + 255) / 256), 256>>>(patch_w, pwh, pwl, npw);
        long long npj = (long long)NLAYER * MFEAT * EDIM;
        convert_pair<<<(unsigned)((npj + 255) / 256), 256>>>(proj, pjh, pjl, npj);
        dim3 blk(32, 8);
        // w1 [l][768][3072] -> [l][3072][768]
        transpose_convert<<<dim3(96, 24, NLAYER), blk>>>(w1, w1h, w1l,
            EDIM, FDIM, (long long)EDIM * FDIM, (long long)EDIM * FDIM);
        // w2 [l][3072][768] -> [l][768][3072]
        transpose_convert<<<dim3(24, 96, NLAYER), blk>>>(w2, w2h, w2l,
            FDIM, EDIM, (long long)EDIM * FDIM, (long long)EDIM * FDIM);
    }

    // --- patch embedding ---
    {
        long long tot = (long long)BSZ * NPATCH * 768;
        im2col_kernel<<<(unsigned)((tot + 255) / 256), 256>>>(x, pt);
        mma_gemm<<<dim3(6, 25, 1), 256, GSMEM>>>(pt, pwh, pwl,
            tok, nullptr, nullptr,
            BSZ * NPATCH, 768, 768, EDIM, 0, 0, 0, 0, 0, 768,
            patch_b, nullptr, 0, 1);
        long long ht = (long long)ROWS * EDIM;
        assemble_kernel<<<(unsigned)((ht + 255) / 256), 256>>>(tok, cls_tok, pos_emb, h);
    }

    for (int l = 0; l < NLAYER; l++) {
        long long pjo = (long long)l * MFEAT * EDIM;
        long long wo  = (long long)l * EDIM * FDIM;
        // LN1 -> y fp32 (+diag)
        ln_kernel<<<(ROWS + 7) / 8, 256>>>(h, EDIM, y, EDIM,
            ln1_g + l * EDIM, ln1_b + l * EDIM, diag, ROWS);
        // logits = y @ proj^T -> lg fp32
        mma_gemm<<<dim3(2, 25, 1), 256, GSMEM>>>(y, pjh + pjo, pjl + pjo,
            lg, nullptr, nullptr,
            ROWS, EDIM, EDIM, MFEAT, 0, 0, 0, 0, 0, EDIM,
            nullptr, nullptr, 0, 0);
        lg_rowmax_kernel<<<ROWS, 256>>>(lg, diag, qmax);
        gmax_kernel<<<1, 256>>>(qmax, gmax);
        feat_kernel<<<(ROWS * MFEAT + 255) / 256, 256>>>(lg, qmax, gmax, qf, kfTh, kfTl);
        ksum_kernel<<<(BSZ * MFEAT * 32 + 255) / 256, 256>>>(kfTh, kfTl, ksum);
        // yT fp32 (zero-padded t>=197, pad never written -> stays 0)
        transpose_tiled<<<dim3(24, 7, BSZ), dim3(32, 8)>>>(y, yT, NTOK, EDIM, KPAD,
            (long long)NTOK * EDIM, (long long)EDIM * KPAD);
        // kvT = yT @ kfT^T -> pair out
        mma_gemm<<<dim3(2, 6, BSZ), 256, GSMEM>>>(yT, kfTh, kfTl,
            nullptr, kvTh, kvTl,
            EDIM, KPAD, KPAD, MFEAT,
            (long long)EDIM * KPAD, (long long)MFEAT * KPAD, (long long)EDIM * MFEAT,
            0, 0, KPAD, nullptr, nullptr, 0, 16);
        den_kernel<<<(ROWS + 7) / 8, 256>>>(qf, ksum, den);
        // h += (qf @ kvT^T) / den
        mma_gemm<<<dim3(6, 2, BSZ), 256, GSMEM>>>(qf, kvTh, kvTl,
            h, nullptr, nullptr,
            NTOK, MFEAT, MFEAT, EDIM,
            (long long)NTOK * MFEAT, (long long)EDIM * MFEAT, (long long)NTOK * EDIM,
            0, 0, MFEAT, nullptr, den, NTOK, 4 | 8);
        // LN2 -> y fp32
        ln_kernel<<<(ROWS + 7) / 8, 256>>>(h, EDIM, y, EDIM,
            ln2_g + l * EDIM, ln2_b + l * EDIM, nullptr, ROWS);
        // hid = gelu(y @ w1 + b1) -> tmp fp32
        mma_gemm<<<dim3(24, 25, 1), 256, GSMEM>>>(y, w1h + wo, w1l + wo,
            tmp, nullptr, nullptr,
            ROWS, EDIM, EDIM, FDIM, 0, 0, 0, 0, 0, EDIM,
            b1 + l * FDIM, nullptr, 0, 1 | 2);
        // part[z] = hid[:, z*1536:] @ w2T[:, z*1536:]^T (split-K over 2)
        mma_gemm<<<dim3(6, 25, 2), 256, GSMEM>>>(tmp, w2h + wo, w2l + wo,
            part, nullptr, nullptr,
            ROWS, FDIM, FDIM, EDIM, 0, 0, (long long)ROWS * EDIM,
            0, FDIM / 2, FDIM / 2, nullptr, nullptr, 0, 0);
        combine_kernel<<<(ROWS * EDIM + 255) / 256, 256>>>(part, b2 + l * EDIM, h);
    }

    // final LN on CLS tokens + head
    ln_kernel<<<2, 256>>>(h, (long long)NTOK * EDIM, clsb, EDIM, lnf_g, lnf_b, nullptr, BSZ);
    {
        dim3 grid(8, 1, 1);
        gemm_kernel<<<grid, 256>>>(clsb, head_w, out,
            BSZ, NC, EDIM, head_b, 1);
    }
}

// round 14
// speedup vs baseline: 1.8256x; 1.2291x over previous
#include <cuda_runtime.h>
#include <cuda_bf16.h>
#include <math.h>
#include <stdint.h>

// ---------------- problem constants ----------------
#define EDIM   768
#define NTOK   197
#define BSZ    16
#define ROWS   (BSZ*NTOK)      // 3152
#define MFEAT  256
#define FDIM   3072
#define NPATCH 196
#define NC     1000
#define NLAYER 12
#define KPAD   224             // 197 padded to mult of 32

#define SCAL  0.18995897f      // 768^{-1/4}
#define MSCL  0.0625f          // 256^{-1/2}
#define FEPS  1e-4f

// ---------------- scratch (device globals; allocation-free) ----------------
__device__ float g_h   [ROWS*EDIM];
__device__ float g_y   [ROWS*EDIM];
__device__ float g_tmp [ROWS*FDIM];          // MLP hidden; im2col+tok at start
__device__ float g_lg  [ROWS*MFEAT];
__device__ float g_qf  [ROWS*MFEAT];
__device__ float g_kfT [BSZ*MFEAT*KPAD];     // [b][m][t] zero-padded t>=197
__device__ float g_yT  [BSZ*EDIM*KPAD];      // [b][e][t] zero-padded
__device__ float g_kvT [BSZ*EDIM*MFEAT];     // [b][e][m]
__device__ float g_part[2*ROWS*EDIM];        // split-K partials
__device__ float g_diag[ROWS];
__device__ float g_qmax[ROWS];
__device__ float g_den [ROWS];
__device__ float g_ksum[BSZ*MFEAT];
__device__ float g_gmax[1];
__device__ float g_cls [BSZ*EDIM];
__device__ float g_w1T [NLAYER*EDIM*FDIM];   // [l][f][e]
__device__ float g_w2T [NLAYER*EDIM*FDIM];   // [l][e][f]

// ================= bf16-split mma.sync GEMM =================
// C[M, N=grid.x*128] = A[M,klen] @ B[N,klen]^T   (both fp32 K-major)
// 2-term bf16 split, 3 products: fp32-like accuracy (~1e-5).
// flags: 1=+bias[n]  2=gelu  4=accumulate into C  8=divide by rowdiv[z*sdiv+m]

#define SPITCH 40   // smem row pitch in halfs (80 bytes): conflict-free for ldmatrix

__device__ __forceinline__ void mma_bf16(float* c, const uint32_t* a, const uint32_t* b)
{
    asm volatile(
        "mma.sync.aligned.m16n8k16.row.col.f32.bf16.bf16.f32 "
        "{%0,%1,%2,%3}, {%4,%5,%6,%7}, {%8,%9}, {%0,%1,%2,%3};"
        : "+f"(c[0]), "+f"(c[1]), "+f"(c[2]), "+f"(c[3])
        : "r"(a[0]), "r"(a[1]), "r"(a[2]), "r"(a[3]), "r"(b[0]), "r"(b[1]));
}

__device__ __forceinline__ uint32_t smem_addr(const void* p)
{
    uint32_t a;
    asm("{ .reg .u64 t; cvta.to.shared.u64 t, %1; cvt.u32.u64 %0, t; }"
        : "=r"(a) : "l"(p));
    return a;
}

__device__ __forceinline__ void ldsm_x4(uint32_t* r, uint32_t addr)
{
    asm volatile("ldmatrix.sync.aligned.m8n8.x4.shared.b16 {%0,%1,%2,%3}, [%4];"
                 : "=r"(r[0]), "=r"(r[1]), "=r"(r[2]), "=r"(r[3]) : "r"(addr));
}
__device__ __forceinline__ void ldsm_x2(uint32_t* r, uint32_t addr)
{
    asm volatile("ldmatrix.sync.aligned.m8n8.x2.shared.b16 {%0,%1}, [%2];"
                 : "=r"(r[0]), "=r"(r[1]) : "r"(addr));
}

// split float4 -> packed hi(2xuint) and lo(2xuint) bf16x2
__device__ __forceinline__ void split_pack(float4 v, uint2& hi, uint2& lo)
{
    __nv_bfloat16 hx = __float2bfloat16(v.x);
    __nv_bfloat16 hy = __float2bfloat16(v.y);
    __nv_bfloat16 hz = __float2bfloat16(v.z);
    __nv_bfloat16 hw = __float2bfloat16(v.w);
    __nv_bfloat16 lx = __float2bfloat16(v.x - __bfloat162float(hx));
    __nv_bfloat16 ly = __float2bfloat16(v.y - __bfloat162float(hy));
    __nv_bfloat16 lz = __float2bfloat16(v.z - __bfloat162float(hz));
    __nv_bfloat16 lw = __float2bfloat16(v.w - __bfloat162float(hw));
    __nv_bfloat162 h0 = __halves2bfloat162(hx, hy);
    __nv_bfloat162 h1 = __halves2bfloat162(hz, hw);
    __nv_bfloat162 l0 = __halves2bfloat162(lx, ly);
    __nv_bfloat162 l1 = __halves2bfloat162(lz, lw);
    hi.x = *(uint32_t*)&h0; hi.y = *(uint32_t*)&h1;
    lo.x = *(uint32_t*)&l0; lo.y = *(uint32_t*)&l1;
}

// 512 threads, 16 warps in 4x4 grid; each warp owns a 32x32 output tile.
__global__ void __launch_bounds__(512) mma_gemm(
    const float* __restrict__ A, const float* __restrict__ B, float* __restrict__ C,
    int M, int ldA, int ldB, int ldC,
    long long sA, long long sB, long long sC,
    int kstart, int kzs, int klen,
    const float* __restrict__ bias, const float* __restrict__ rowdiv, int sdiv, int flags)
{
    __shared__ __align__(16) __nv_bfloat16 Ah[128 * SPITCH];
    __shared__ __align__(16) __nv_bfloat16 Al[128 * SPITCH];
    __shared__ __align__(16) __nv_bfloat16 Bh[128 * SPITCH];
    __shared__ __align__(16) __nv_bfloat16 Bl[128 * SPITCH];

    int tid = threadIdx.x;
    int wid = tid >> 5, lane = tid & 31;
    int m0 = blockIdx.y * 128, n0 = blockIdx.x * 128, z = blockIdx.z;
    int warpM = wid >> 2;          // 0..3 -> 32 rows each
    int warpN = wid & 3;           // 0..3 -> 32 cols each
    int qr = lane >> 2;            // group row 0..7
    int qc = (lane & 3) * 2;       // k pair base

    // ldmatrix per-lane byte offsets
    uint32_t AhB = smem_addr(Ah), AlB = smem_addr(Al);
    uint32_t BhB = smem_addr(Bh), BlB = smem_addr(Bl);
    uint32_t aoff = (uint32_t)(((warpM * 32 + (lane & 15)) * SPITCH + ((lane >> 4) << 3)) * 2);
    uint32_t boff = (uint32_t)(((warpN * 32 + (lane & 7)) * SPITCH + (((lane >> 3) & 1) << 3)) * 2);

    const float* Ab = A + (long long)z * sA + kstart + (long long)z * kzs;
    const float* Bb = B + (long long)z * sB + kstart + (long long)z * kzs;

    float acc[2][4][4];
#pragma unroll
    for (int i = 0; i < 2; i++)
#pragma unroll
        for (int j = 0; j < 4; j++)
#pragma unroll
            for (int r = 0; r < 4; r++) acc[i][j][r] = 0.f;

    int kt_n = klen >> 5;

    // prefetch tile 0 into regs (each thread: 2 float4 of A, 2 of B)
    float4 av[2], bv[2];
#pragma unroll
    for (int i = 0; i < 2; i++) {
        int idx = tid + (i << 9);
        int r = idx >> 3, c4 = idx & 7;
        int gm = m0 + r;
        av[i] = (gm < M) ? *(const float4*)(Ab + (long long)gm * ldA + (c4 << 2))
                         : make_float4(0.f, 0.f, 0.f, 0.f);
        bv[i] = *(const float4*)(Bb + (long long)(n0 + r) * ldB + (c4 << 2));
    }

    for (int kt = 0; kt < kt_n; kt++) {
        __syncthreads();   // previous compute done; smem reusable
        // convert + store current tile
#pragma unroll
        for (int i = 0; i < 2; i++) {
            int idx = tid + (i << 9);
            int r = idx >> 3, c4 = idx & 7;
            int ho = r * SPITCH + c4 * 4;
            uint2 hi, lo;
            split_pack(av[i], hi, lo);
            *(uint2*)&Ah[ho] = hi; *(uint2*)&Al[ho] = lo;
            split_pack(bv[i], hi, lo);
            *(uint2*)&Bh[ho] = hi; *(uint2*)&Bl[ho] = lo;
        }
        __syncthreads();
        // prefetch next tile
        if (kt + 1 < kt_n) {
            long long ko = ((long long)(kt + 1) << 5);
#pragma unroll
            for (int i = 0; i < 2; i++) {
                int idx = tid + (i << 9);
                int r = idx >> 3, c4 = idx & 7;
                int gm = m0 + r;
                av[i] = (gm < M) ? *(const float4*)(Ab + (long long)gm * ldA + ko + (c4 << 2))
                                 : make_float4(0.f, 0.f, 0.f, 0.f);
                bv[i] = *(const float4*)(Bb + (long long)(n0 + r) * ldB + ko + (c4 << 2));
            }
        }
        // compute 32-deep K slab
#pragma unroll
        for (int ks = 0; ks < 2; ks++) {
            uint32_t kbyte = (uint32_t)(ks * 16 * 2);
            uint32_t bhf[4][2], blf[4][2];
#pragma unroll
            for (int nt = 0; nt < 4; nt++) {
                uint32_t bo = boff + (uint32_t)(nt * 8 * SPITCH * 2) + kbyte;
                ldsm_x2(bhf[nt], BhB + bo);
                ldsm_x2(blf[nt], BlB + bo);
            }
#pragma unroll
            for (int mt = 0; mt < 2; mt++) {
                uint32_t ao = aoff + (uint32_t)(mt * 16 * SPITCH * 2) + kbyte;
                uint32_t ahf[4], alf[4];
                ldsm_x4(ahf, AhB + ao);
                ldsm_x4(alf, AlB + ao);
#pragma unroll
                for (int nt = 0; nt < 4; nt++) {
                    mma_bf16(acc[mt][nt], ahf, bhf[nt]);
                    mma_bf16(acc[mt][nt], ahf, blf[nt]);
                    mma_bf16(acc[mt][nt], alf, bhf[nt]);
                }
            }
        }
    }

    // ---- epilogue ----
#pragma unroll
    for (int mt = 0; mt < 2; mt++) {
        int r0 = m0 + warpM * 32 + mt * 16 + qr;
        int r1 = r0 + 8;
        bool ok0 = r0 < M, ok1 = r1 < M;
        float dv0 = 1.f, dv1 = 1.f;
        if (flags & 8) {
            if (ok0) dv0 = 1.f / rowdiv[(long long)z * sdiv + r0];
            if (ok1) dv1 = 1.f / rowdiv[(long long)z * sdiv + r1];
        }
        float* row0 = C + (long long)z * sC + (long long)r0 * ldC;
        float* row1 = C + (long long)z * sC + (long long)r1 * ldC;
#pragma unroll
        for (int nt = 0; nt < 4; nt++) {
            int col = n0 + warpN * 32 + nt * 8 + qc;
            float b0 = 0.f, b1 = 0.f;
            if (flags & 1) { b0 = bias[col]; b1 = bias[col + 1]; }
#pragma unroll
            for (int half = 0; half < 2; half++) {
                bool ok = half ? ok1 : ok0;
                if (!ok) continue;
                float dv = half ? dv1 : dv0;
                float* row = half ? row1 : row0;
                float v0 = acc[mt][nt][half * 2 + 0];
                float v1 = acc[mt][nt][half * 2 + 1];
                v0 += b0; v1 += b1;
                if (flags & 2) {
                    v0 = 0.5f * v0 * (1.f + erff(v0 * 0.70710678118654752f));
                    v1 = 0.5f * v1 * (1.f + erff(v1 * 0.70710678118654752f));
                }
                if (flags & 8) { v0 *= dv; v1 *= dv; }
                if (flags & 4) { v0 += row[col]; v1 += row[col + 1]; }
                row[col] = v0; row[col + 1] = v1;
            }
        }
    }
}

// ================= fallback SGEMM (head only) =================
__global__ void __launch_bounds__(256) gemm_kernel(
    const float* __restrict__ A, const float* __restrict__ B, float* __restrict__ C,
    int M, int N, int K,
    const float* __restrict__ bias, int flags)
{
    __shared__ __align__(16) float As[8][128];
    __shared__ __align__(16) float Bs[8][128];
    int tid = threadIdx.x;
    int m0 = blockIdx.y * 128;
    int n0 = blockIdx.x * 128;
    int tx = tid & 15, ty = tid >> 4;
    float acc[8][8];
#pragma unroll
    for (int i = 0; i < 8; i++)
#pragma unroll
        for (int j = 0; j < 8; j++) acc[i][j] = 0.f;
    for (int k0 = 0; k0 < K; k0 += 8) {
#pragma unroll
        for (int i = 0; i < 4; i++) {
            int l = tid + i * 256;
            int mm = l >> 3, kk = l & 7;
            int gk = k0 + kk, gm = m0 + mm;
            As[kk][mm] = (gk < K && gm < M) ? A[(long long)gm * K + gk] : 0.f;
        }
#pragma unroll
        for (int i = 0; i < 4; i++) {
            int l = tid + i * 256;
            int kk = l >> 7, nn = l & 127;
            int gk = k0 + kk, gn = n0 + nn;
            Bs[kk][nn] = (gk < K && gn < N) ? B[(long long)gk * N + gn] : 0.f;
        }
        __syncthreads();
#pragma unroll
        for (int k = 0; k < 8; k++) {
            float4 a0 = *(const float4*)&As[k][ty * 4];
            float4 a1 = *(const float4*)&As[k][ty * 4 + 64];
            float4 b0 = *(const float4*)&Bs[k][tx * 4];
            float4 b1 = *(const float4*)&Bs[k][tx * 4 + 64];
            float af[8] = {a0.x, a0.y, a0.z, a0.w, a1.x, a1.y, a1.z, a1.w};
            float bf_[8] = {b0.x, b0.y, b0.z, b0.w, b1.x, b1.y, b1.z, b1.w};
#pragma unroll
            for (int i = 0; i < 8; i++)
#pragma unroll
                for (int j = 0; j < 8; j++) acc[i][j] += af[i] * bf_[j];
        }
        __syncthreads();
    }
#pragma unroll
    for (int i = 0; i < 8; i++) {
        int gm = m0 + ((i < 4) ? ty * 4 + i : 64 + ty * 4 + (i - 4));
        if (gm >= M) continue;
        float* crow = C + (long long)gm * N;
#pragma unroll
        for (int j = 0; j < 8; j++) {
            int gn = n0 + ((j < 4) ? tx * 4 + j : 64 + tx * 4 + (j - 4));
            if (gn >= N) continue;
            float v = acc[i][j];
            if (flags & 1) v += bias[gn];
            crow[gn] = v;
        }
    }
}

// ================= layernorm: warp per row =================
__global__ void ln_kernel(const float* __restrict__ X, long long ldx,
                          float* __restrict__ Y, long long ldy,
                          const float* __restrict__ g, const float* __restrict__ b,
                          float* __restrict__ diag, int nrows)
{
    int w = blockIdx.x * (blockDim.x >> 5) + (threadIdx.x >> 5);
    int lane = threadIdx.x & 31;
    if (w >= nrows) return;
    const float4* x = (const float4*)(X + (long long)w * ldx);
    float4 v[6];
    float s1 = 0.f, s2 = 0.f;
#pragma unroll
    for (int i = 0; i < 6; i++) {
        v[i] = x[lane + 32 * i];
        s1 += v[i].x + v[i].y + v[i].z + v[i].w;
        s2 += v[i].x * v[i].x + v[i].y * v[i].y + v[i].z * v[i].z + v[i].w * v[i].w;
    }
#pragma unroll
    for (int o = 16; o > 0; o >>= 1) {
        s1 += __shfl_xor_sync(0xffffffffu, s1, o);
        s2 += __shfl_xor_sync(0xffffffffu, s2, o);
    }
    float mu  = s1 * (1.0f / 768.0f);
    float var = s2 * (1.0f / 768.0f) - mu * mu;
    float inv = rsqrtf(var + 1e-5f);
    const float4* g4 = (const float4*)g;
    const float4* b4 = (const float4*)b;
    float4* y4 = (float4*)(Y + (long long)w * ldy);
    float d = 0.f;
#pragma unroll
    for (int i = 0; i < 6; i++) {
        float4 gv = g4[lane + 32 * i], bv = b4[lane + 32 * i], o;
        o.x = (v[i].x - mu) * inv * gv.x + bv.x;
        o.y = (v[i].y - mu) * inv * gv.y + bv.y;
        o.z = (v[i].z - mu) * inv * gv.z + bv.z;
        o.w = (v[i].w - mu) * inv * gv.w + bv.w;
        d += o.x * o.x + o.y * o.y + o.z * o.z + o.w * o.w;
        y4[lane + 32 * i] = o;
    }
    if (diag) {
#pragma unroll
        for (int o = 16; o > 0; o >>= 1) d += __shfl_xor_sync(0xffffffffu, d, o);
        if (lane == 0) diag[w] = 0.5f * SCAL * SCAL * d;
    }
}

// ================= performer helpers =================
__global__ void lg_rowmax_kernel(float* __restrict__ lg, const float* __restrict__ diag,
                                 float* __restrict__ qmax)
{
    int row = blockIdx.x;
    int tid = threadIdx.x;
    long long idx = (long long)row * MFEAT + tid;
    float v = lg[idx] * SCAL - diag[row];
    lg[idx] = v;
    __shared__ float red[8];
    float m = v;
#pragma unroll
    for (int o = 16; o > 0; o >>= 1) m = fmaxf(m, __shfl_down_sync(0xffffffffu, m, o));
    int w = tid >> 5, lane = tid & 31;
    if (lane == 0) red[w] = m;
    __syncthreads();
    if (tid == 0) {
        float a = red[0];
        for (int i = 1; i < 8; i++) a = fmaxf(a, red[i]);
        qmax[row] = a;
    }
}

__global__ void gmax_kernel(const float* __restrict__ qmax, float* __restrict__ gmax)
{
    int tid = threadIdx.x;
    float m = -1e30f;
    for (int i = tid; i < ROWS; i += 256) m = fmaxf(m, qmax[i]);
    __shared__ float red[8];
#pragma unroll
    for (int o = 16; o > 0; o >>= 1) m = fmaxf(m, __shfl_down_sync(0xffffffffu, m, o));
    int w = tid >> 5, lane = tid & 31;
    if (lane == 0) red[w] = m;
    __syncthreads();
    if (tid == 0) {
        float a = red[0];
        for (int i = 1; i < 8; i++) a = fmaxf(a, red[i]);
        gmax[0] = a;
    }
}

__global__ void feat_kernel(const float* __restrict__ lg, const float* __restrict__ qmax,
                            const float* __restrict__ gmax,
                            float* __restrict__ qf, float* __restrict__ kfT)
{
    long long i = (long long)blockIdx.x * 256 + threadIdx.x;
    if (i >= (long long)ROWS * MFEAT) return;
    int tg = (int)(i >> 8);
    int m = (int)(i & 255);
    int b = tg / NTOK;
    int t = tg - b * NTOK;
    float v = lg[i];
    qf[i] = expf(v - qmax[tg]) * MSCL + FEPS;
    kfT[((long long)(b * MFEAT + m)) * KPAD + t] = expf(v - gmax[0]) * MSCL + FEPS;
}

__global__ void ksum_kernel(const float* __restrict__ kfT, float* __restrict__ ksum)
{
    int w = (blockIdx.x * blockDim.x + threadIdx.x) >> 5;
    int lane = threadIdx.x & 31;
    if (w >= BSZ * MFEAT) return;
    const float* p = kfT + (long long)w * KPAD;
    float s = 0.f;
#pragma unroll
    for (int t = lane; t < KPAD; t += 32) s += p[t];
#pragma unroll
    for (int o = 16; o > 0; o >>= 1) s += __shfl_down_sync(0xffffffffu, s, o);
    if (lane == 0) ksum[w] = s;
}

__global__ void den_kernel(const float* __restrict__ qf, const float* __restrict__ ksum,
                           float* __restrict__ den)
{
    int warp = (blockIdx.x * blockDim.x + threadIdx.x) >> 5;
    int lane = threadIdx.x & 31;
    if (warp >= ROWS) return;
    int b = warp / NTOK;
    const float* q  = qf + (long long)warp * MFEAT;
    const float* ks = ksum + b * MFEAT;
    float s = 0.f;
#pragma unroll
    for (int m = lane; m < MFEAT; m += 32) s += q[m] * ks[m];
#pragma unroll
    for (int o = 16; o > 0; o >>= 1) s += __shfl_down_sync(0xffffffffu, s, o);
    if (lane == 0) den[warp] = s;
}

// ================= transpose (tiled) =================
__global__ void transpose_tiled(const float* __restrict__ in, float* __restrict__ out,
                                int R, int Ccol, int ldo, long long sin, long long sout)
{
    __shared__ float t[32][33];
    const float* ip = in + (long long)blockIdx.z * sin;
    float* op = out + (long long)blockIdx.z * sout;
    int c0 = blockIdx.x * 32, r0 = blockIdx.y * 32;
    int tx = threadIdx.x, ty = threadIdx.y;
#pragma unroll
    for (int k = 0; k < 4; k++) {
        int r = r0 + ty + 8 * k;
        if (r < R && c0 + tx < Ccol)
            t[ty + 8 * k][tx] = ip[(long long)r * Ccol + c0 + tx];
    }
    __syncthreads();
#pragma unroll
    for (int k = 0; k < 4; k++) {
        int c = c0 + ty + 8 * k;
        int r = r0 + tx;
        if (c < Ccol && r < R)
            op[(long long)c * ldo + r] = t[tx][ty + 8 * k];
    }
}

// ================= misc elementwise =================
__global__ void im2col_kernel(const float* __restrict__ x, float* __restrict__ pt)
{
    long long i = (long long)blockIdx.x * 256 + threadIdx.x;
    if (i >= (long long)BSZ * NPATCH * 768) return;
    int kidx = (int)(i % 768);
    int p    = (int)(i / 768);
    int pj = kidx & 15, pi = (kidx >> 4) & 15, c = kidx >> 8;
    int gj = p % 14;
    int t  = p / 14;
    int gi = t % 14;
    int b  = t / 14;
    pt[i] = x[(((long long)(b * 3 + c) * 224 + gi * 16 + pi) * 224) + gj * 16 + pj];
}

__global__ void assemble_kernel(const float* __restrict__ tok, const float* __restrict__ cls_tok,
                                const float* __restrict__ pos, float* __restrict__ h)
{
    long long i = (long long)blockIdx.x * 256 + threadIdx.x;
    if (i >= (long long)ROWS * EDIM) return;
    int e = (int)(i % EDIM);
    int t = (int)(i / EDIM);
    int n = t % NTOK;
    int b = t / NTOK;
    float v = (n == 0) ? cls_tok[e] : tok[(long long)(b * NPATCH + n - 1) * EDIM + e];
    h[i] = v + pos[(long long)n * EDIM + e];
}

__global__ void combine_kernel(const float* __restrict__ part, const float* __restrict__ b2,
                               float* __restrict__ h)
{
    long long i = (long long)blockIdx.x * 256 + threadIdx.x;
    if (i >= (long long)ROWS * EDIM) return;
    int e = (int)(i % EDIM);
    h[i] += part[i] + part[(long long)ROWS * EDIM + i] + b2[e];
}

// ================= host =================
static inline float* sym(const void* s)
{
    void* p = nullptr;
    cudaGetSymbolAddress(&p, s);
    return (float*)p;
}

extern "C" void kernel_launch(void* const* d_in, const int* in_sizes, int n_in,
                              void* d_out, int out_size)
{
    const float* x       = (const float*)d_in[0];
    const float* cls_tok = (const float*)d_in[1];
    const float* pos_emb = (const float*)d_in[2];
    const float* patch_w = (const float*)d_in[3];
    const float* patch_b = (const float*)d_in[4];
    const float* ln1_g   = (const float*)d_in[5];
    const float* ln1_b   = (const float*)d_in[6];
    const float* proj    = (const float*)d_in[7];
    const float* ln2_g   = (const float*)d_in[8];
    const float* ln2_b   = (const float*)d_in[9];
    const float* w1      = (const float*)d_in[10];
    const float* b1      = (const float*)d_in[11];
    const float* w2      = (const float*)d_in[12];
    const float* b2      = (const float*)d_in[13];
    const float* lnf_g   = (const float*)d_in[14];
    const float* lnf_b   = (const float*)d_in[15];
    const float* head_w  = (const float*)d_in[16];
    const float* head_b  = (const float*)d_in[17];
    float* out = (float*)d_out;

    float* h    = sym(g_h);
    float* y    = sym(g_y);
    float* tmp  = sym(g_tmp);
    float* lg   = sym(g_lg);
    float* qf   = sym(g_qf);
    float* kfT  = sym(g_kfT);
    float* yT   = sym(g_yT);
    float* kvT  = sym(g_kvT);
    float* part = sym(g_part);
    float* diag = sym(g_diag);
    float* qmax = sym(g_qmax);
    float* den  = sym(g_den);
    float* ksum = sym(g_ksum);
    float* gmax = sym(g_gmax);
    float* clsb = sym(g_cls);
    float* w1T  = sym(g_w1T);
    float* w2T  = sym(g_w2T);

    float* pt  = tmp;             // [3136,768] im2col
    float* tok = tmp + 5000000;   // [3136,768] patch-embed out

    // --- weight transposes (w1T[l]: [3072,768], w2T[l]: [768,3072]) ---
    {
        dim3 blk(32, 8);
        transpose_tiled<<<dim3(96, 24, NLAYER), blk>>>(w1, w1T, EDIM, FDIM, EDIM,
            (long long)EDIM * FDIM, (long long)EDIM * FDIM);
        transpose_tiled<<<dim3(24, 96, NLAYER), blk>>>(w2, w2T, FDIM, EDIM, FDIM,
            (long long)EDIM * FDIM, (long long)EDIM * FDIM);
    }

    // --- patch embedding ---
    {
        long long tot = (long long)BSZ * NPATCH * 768;
        im2col_kernel<<<(unsigned)((tot + 255) / 256), 256>>>(x, pt);
        mma_gemm<<<dim3(6, 25, 1), 512>>>(pt, patch_w, tok,
            BSZ * NPATCH, 768, 768, EDIM, 0, 0, 0, 0, 0, 768,
            patch_b, nullptr, 0, 1);
        long long ht = (long long)ROWS * EDIM;
        assemble_kernel<<<(unsigned)((ht + 255) / 256), 256>>>(tok, cls_tok, pos_emb, h);
    }

    for (int l = 0; l < NLAYER; l++) {
        const float* prj = proj + (long long)l * MFEAT * EDIM;
        // LN1 + diag
        ln_kernel<<<(ROWS + 7) / 8, 256>>>(h, EDIM, y, EDIM,
            ln1_g + l * EDIM, ln1_b + l * EDIM, diag, ROWS);
        // logits = y @ proj^T (raw)
        mma_gemm<<<dim3(2, 25, 1), 512>>>(y, prj, lg,
            ROWS, EDIM, EDIM, MFEAT, 0, 0, 0, 0, 0, EDIM,
            nullptr, nullptr, 0, 0);
        lg_rowmax_kernel<<<ROWS, 256>>>(lg, diag, qmax);
        gmax_kernel<<<1, 256>>>(qmax, gmax);
        feat_kernel<<<(ROWS * MFEAT + 255) / 256, 256>>>(lg, qmax, gmax, qf, kfT);
        ksum_kernel<<<(BSZ * MFEAT * 32 + 255) / 256, 256>>>(kfT, ksum);
        // yT[b][e][t] (zero-padded t>=197)
        transpose_tiled<<<dim3(24, 7, BSZ), dim3(32, 8)>>>(y, yT, NTOK, EDIM, KPAD,
            (long long)NTOK * EDIM, (long long)EDIM * KPAD);
        // kvT[b] = yT[b] @ kfT[b]^T : [768,256], K=224
        mma_gemm<<<dim3(2, 6, BSZ), 512>>>(yT, kfT, kvT,
            EDIM, KPAD, KPAD, MFEAT,
            (long long)EDIM * KPAD, (long long)MFEAT * KPAD, (long long)EDIM * MFEAT,
            0, 0, KPAD, nullptr, nullptr, 0, 0);
        den_kernel<<<(ROWS + 7) / 8, 256>>>(qf, ksum, den);
        // h += (qf @ kvT^T) / den
        mma_gemm<<<dim3(6, 2, BSZ), 512>>>(qf, kvT, h,
            NTOK, MFEAT, MFEAT, EDIM,
            (long long)NTOK * MFEAT, (long long)EDIM * MFEAT, (long long)NTOK * EDIM,
            0, 0, MFEAT, nullptr, den, NTOK, 4 | 8);
        // LN2
        ln_kernel<<<(ROWS + 7) / 8, 256>>>(h, EDIM, y, EDIM,
            ln2_g + l * EDIM, ln2_b + l * EDIM, nullptr, ROWS);
        // hid = gelu(y @ w1 + b1)
        mma_gemm<<<dim3(24, 25, 1), 512>>>(y, w1T + (long long)l * EDIM * FDIM, tmp,
            ROWS, EDIM, EDIM, FDIM, 0, 0, 0, 0, 0, EDIM,
            b1 + l * FDIM, nullptr, 0, 1 | 2);
        // part[z] = hid[:, zK:] @ w2T[:, zK:]^T   (split-K over 2)
        mma_gemm<<<dim3(6, 25, 2), 512>>>(tmp, w2T + (long long)l * EDIM * FDIM, part,
            ROWS, FDIM, FDIM, EDIM, 0, 0, (long long)ROWS * EDIM,
            0, FDIM / 2, FDIM / 2, nullptr, nullptr, 0, 0);
        combine_kernel<<<(ROWS * EDIM + 255) / 256, 256>>>(part, b2 + l * EDIM, h);
    }

    // final LN on CLS tokens + head
    ln_kernel<<<2, 256>>>(h, (long long)NTOK * EDIM, clsb, EDIM, lnf_g, lnf_b, nullptr, BSZ);
    {
        dim3 grid(8, 1, 1);
        gemm_kernel<<<grid, 256>>>(clsb, head_w, out,
            BSZ, NC, EDIM, head_b, 1);
    }
}

// round 16
// speedup vs baseline: 1.9860x; 1.0878x over previous
#include <cuda_runtime.h>
#include <cuda_bf16.h>
#include <math.h>
#include <stdint.h>

// ---------------- problem constants ----------------
#define EDIM   768
#define NTOK   197
#define BSZ    16
#define ROWS   (BSZ*NTOK)      // 3152
#define MFEAT  256
#define FDIM   3072
#define NPATCH 196
#define NC     1000
#define NLAYER 12
#define KPAD   224             // 197 padded to mult of 32

#define SCAL  0.18995897f      // 768^{-1/4}
#define MSCL  0.0625f          // 256^{-1/2}
#define FEPS  1e-4f

// ---------------- scratch (device globals; allocation-free) ----------------
__device__ float g_h   [ROWS*EDIM];
__device__ float g_y   [ROWS*EDIM];
__device__ float g_tmp [ROWS*FDIM];          // MLP hidden; im2col+tok at start
__device__ float g_lg  [ROWS*MFEAT];
__device__ float g_qf  [ROWS*MFEAT];
__device__ float g_kfT [BSZ*MFEAT*KPAD];     // [b][m][t] zero-padded t>=197
__device__ float g_yT  [BSZ*EDIM*KPAD];      // [b][e][t] zero-padded
__device__ float g_kvT [BSZ*EDIM*MFEAT];     // [b][e][m]
__device__ float g_part[2*ROWS*EDIM];        // split-K partials
__device__ float g_diag[ROWS];
__device__ float g_qmax[ROWS];
__device__ float g_den [ROWS];
__device__ float g_ksum[BSZ*MFEAT];
__device__ float g_gmax[1];
__device__ float g_cls [BSZ*EDIM];
__device__ float g_w1T [NLAYER*EDIM*FDIM];   // [l][f][e]
__device__ float g_w2T [NLAYER*EDIM*FDIM];   // [l][e][f]

// ================= bf16-split mma.sync GEMM =================
// C[M, N=grid.x*128] = A[M,klen] @ B[N,klen]^T   (both fp32 K-major)
// 2-term bf16 split, 3 products: fp32-like accuracy (~1e-5).
// CTA tile: 64(M) x 128(N); 256 threads, 8 warps in 2x4 grid (each 32x32).
// __launch_bounds__(256,2) -> 2 CTAs/SM for cross-CTA latency hiding.
// flags: 1=+bias[n]  2=gelu  4=accumulate into C  8=divide by rowdiv[z*sdiv+m]

#define SPITCH 40   // smem row pitch in halfs (80 bytes): conflict-free for ldmatrix

__device__ __forceinline__ void mma_bf16(float* c, const uint32_t* a, const uint32_t* b)
{
    asm volatile(
        "mma.sync.aligned.m16n8k16.row.col.f32.bf16.bf16.f32 "
        "{%0,%1,%2,%3}, {%4,%5,%6,%7}, {%8,%9}, {%0,%1,%2,%3};"
        : "+f"(c[0]), "+f"(c[1]), "+f"(c[2]), "+f"(c[3])
        : "r"(a[0]), "r"(a[1]), "r"(a[2]), "r"(a[3]), "r"(b[0]), "r"(b[1]));
}

__device__ __forceinline__ uint32_t smem_addr(const void* p)
{
    uint32_t a;
    asm("{ .reg .u64 t; cvta.to.shared.u64 t, %1; cvt.u32.u64 %0, t; }"
        : "=r"(a) : "l"(p));
    return a;
}

__device__ __forceinline__ void ldsm_x4(uint32_t* r, uint32_t addr)
{
    asm volatile("ldmatrix.sync.aligned.m8n8.x4.shared.b16 {%0,%1,%2,%3}, [%4];"
                 : "=r"(r[0]), "=r"(r[1]), "=r"(r[2]), "=r"(r[3]) : "r"(addr));
}
__device__ __forceinline__ void ldsm_x2(uint32_t* r, uint32_t addr)
{
    asm volatile("ldmatrix.sync.aligned.m8n8.x2.shared.b16 {%0,%1}, [%2];"
                 : "=r"(r[0]), "=r"(r[1]) : "r"(addr));
}

// split float4 -> packed hi(2xuint) and lo(2xuint) bf16x2
__device__ __forceinline__ void split_pack(float4 v, uint2& hi, uint2& lo)
{
    __nv_bfloat16 hx = __float2bfloat16(v.x);
    __nv_bfloat16 hy = __float2bfloat16(v.y);
    __nv_bfloat16 hz = __float2bfloat16(v.z);
    __nv_bfloat16 hw = __float2bfloat16(v.w);
    __nv_bfloat16 lx = __float2bfloat16(v.x - __bfloat162float(hx));
    __nv_bfloat16 ly = __float2bfloat16(v.y - __bfloat162float(hy));
    __nv_bfloat16 lz = __float2bfloat16(v.z - __bfloat162float(hz));
    __nv_bfloat16 lw = __float2bfloat16(v.w - __bfloat162float(hw));
    __nv_bfloat162 h0 = __halves2bfloat162(hx, hy);
    __nv_bfloat162 h1 = __halves2bfloat162(hz, hw);
    __nv_bfloat162 l0 = __halves2bfloat162(lx, ly);
    __nv_bfloat162 l1 = __halves2bfloat162(lz, lw);
    hi.x = *(uint32_t*)&h0; hi.y = *(uint32_t*)&h1;
    lo.x = *(uint32_t*)&l0; lo.y = *(uint32_t*)&l1;
}

__global__ void __launch_bounds__(256, 2) mma_gemm(
    const float* __restrict__ A, const float* __restrict__ B, float* __restrict__ C,
    int M, int ldA, int ldB, int ldC,
    long long sA, long long sB, long long sC,
    int kstart, int kzs, int klen,
    const float* __restrict__ bias, const float* __restrict__ rowdiv, int sdiv, int flags)
{
    __shared__ __align__(16) __nv_bfloat16 Ah[64 * SPITCH];
    __shared__ __align__(16) __nv_bfloat16 Al[64 * SPITCH];
    __shared__ __align__(16) __nv_bfloat16 Bh[128 * SPITCH];
    __shared__ __align__(16) __nv_bfloat16 Bl[128 * SPITCH];

    int tid = threadIdx.x;
    int wid = tid >> 5, lane = tid & 31;
    int m0 = blockIdx.y * 64, n0 = blockIdx.x * 128, z = blockIdx.z;
    int warpM = wid >> 2;          // 0..1 -> 32 rows each
    int warpN = wid & 3;           // 0..3 -> 32 cols each
    int qr = lane >> 2;            // group row 0..7
    int qc = (lane & 3) * 2;       // k pair base

    // ldmatrix per-lane byte offsets
    uint32_t AhB = smem_addr(Ah), AlB = smem_addr(Al);
    uint32_t BhB = smem_addr(Bh), BlB = smem_addr(Bl);
    uint32_t aoff = (uint32_t)(((warpM * 32 + (lane & 15)) * SPITCH + ((lane >> 4) << 3)) * 2);
    uint32_t boff = (uint32_t)(((warpN * 32 + (lane & 7)) * SPITCH + (((lane >> 3) & 1) << 3)) * 2);

    const float* Ab = A + (long long)z * sA + kstart + (long long)z * kzs;
    const float* Bb = B + (long long)z * sB + kstart + (long long)z * kzs;

    float acc[2][4][4];
#pragma unroll
    for (int i = 0; i < 2; i++)
#pragma unroll
        for (int j = 0; j < 4; j++)
#pragma unroll
            for (int r = 0; r < 4; r++) acc[i][j][r] = 0.f;

    int kt_n = klen >> 5;

    // prefetch tile 0 into regs (A: 2 float4/thread over 64 rows, B: 4 over 128)
    float4 av[2], bv[4];
#pragma unroll
    for (int i = 0; i < 2; i++) {
        int idx = tid + (i << 8);
        int r = idx >> 3, c4 = idx & 7;
        int gm = m0 + r;
        av[i] = (gm < M) ? *(const float4*)(Ab + (long long)gm * ldA + (c4 << 2))
                         : make_float4(0.f, 0.f, 0.f, 0.f);
    }
#pragma unroll
    for (int i = 0; i < 4; i++) {
        int idx = tid + (i << 8);
        int r = idx >> 3, c4 = idx & 7;
        bv[i] = *(const float4*)(Bb + (long long)(n0 + r) * ldB + (c4 << 2));
    }

    for (int kt = 0; kt < kt_n; kt++) {
        __syncthreads();   // previous compute done; smem reusable
        // convert + store current tile
#pragma unroll
        for (int i = 0; i < 2; i++) {
            int idx = tid + (i << 8);
            int r = idx >> 3, c4 = idx & 7;
            int ho = r * SPITCH + c4 * 4;
            uint2 hi, lo;
            split_pack(av[i], hi, lo);
            *(uint2*)&Ah[ho] = hi; *(uint2*)&Al[ho] = lo;
        }
#pragma unroll
        for (int i = 0; i < 4; i++) {
            int idx = tid + (i << 8);
            int r = idx >> 3, c4 = idx & 7;
            int ho = r * SPITCH + c4 * 4;
            uint2 hi, lo;
            split_pack(bv[i], hi, lo);
            *(uint2*)&Bh[ho] = hi; *(uint2*)&Bl[ho] = lo;
        }
        __syncthreads();
        // prefetch next tile
        if (kt + 1 < kt_n) {
            long long ko = ((long long)(kt + 1) << 5);
#pragma unroll
            for (int i = 0; i < 2; i++) {
                int idx = tid + (i << 8);
                int r = idx >> 3, c4 = idx & 7;
                int gm = m0 + r;
                av[i] = (gm < M) ? *(const float4*)(Ab + (long long)gm * ldA + ko + (c4 << 2))
                                 : make_float4(0.f, 0.f, 0.f, 0.f);
            }
#pragma unroll
            for (int i = 0; i < 4; i++) {
                int idx = tid + (i << 8);
                int r = idx >> 3, c4 = idx & 7;
                bv[i] = *(const float4*)(Bb + (long long)(n0 + r) * ldB + ko + (c4 << 2));
            }
        }
        // compute 32-deep K slab
#pragma unroll
        for (int ks = 0; ks < 2; ks++) {
            uint32_t kbyte = (uint32_t)(ks * 16 * 2);
            uint32_t bhf[4][2], blf[4][2];
#pragma unroll
            for (int nt = 0; nt < 4; nt++) {
                uint32_t bo = boff + (uint32_t)(nt * 8 * SPITCH * 2) + kbyte;
                ldsm_x2(bhf[nt], BhB + bo);
                ldsm_x2(blf[nt], BlB + bo);
            }
#pragma unroll
            for (int mt = 0; mt < 2; mt++) {
                uint32_t ao = aoff + (uint32_t)(mt * 16 * SPITCH * 2) + kbyte;
                uint32_t ahf[4], alf[4];
                ldsm_x4(ahf, AhB + ao);
                ldsm_x4(alf, AlB + ao);
#pragma unroll
                for (int nt = 0; nt < 4; nt++) {
                    mma_bf16(acc[mt][nt], ahf, bhf[nt]);
                    mma_bf16(acc[mt][nt], ahf, blf[nt]);
                    mma_bf16(acc[mt][nt], alf, bhf[nt]);
                }
            }
        }
    }

    // ---- epilogue ----
#pragma unroll
    for (int mt = 0; mt < 2; mt++) {
        int r0 = m0 + warpM * 32 + mt * 16 + qr;
        int r1 = r0 + 8;
        bool ok0 = r0 < M, ok1 = r1 < M;
        float dv0 = 1.f, dv1 = 1.f;
        if (flags & 8) {
            if (ok0) dv0 = 1.f / rowdiv[(long long)z * sdiv + r0];
            if (ok1) dv1 = 1.f / rowdiv[(long long)z * sdiv + r1];
        }
        float* row0 = C + (long long)z * sC + (long long)r0 * ldC;
        float* row1 = C + (long long)z * sC + (long long)r1 * ldC;
#pragma unroll
        for (int nt = 0; nt < 4; nt++) {
            int col = n0 + warpN * 32 + nt * 8 + qc;
            float b0 = 0.f, b1 = 0.f;
            if (flags & 1) { b0 = bias[col]; b1 = bias[col + 1]; }
#pragma unroll
            for (int half = 0; half < 2; half++) {
                bool ok = half ? ok1 : ok0;
                if (!ok) continue;
                float dv = half ? dv1 : dv0;
                float* row = half ? row1 : row0;
                float v0 = acc[mt][nt][half * 2 + 0];
                float v1 = acc[mt][nt][half * 2 + 1];
                v0 += b0; v1 += b1;
                if (flags & 2) {
                    v0 = 0.5f * v0 * (1.f + erff(v0 * 0.70710678118654752f));
                    v1 = 0.5f * v1 * (1.f + erff(v1 * 0.70710678118654752f));
                }
                if (flags & 8) { v0 *= dv; v1 *= dv; }
                if (flags & 4) { v0 += row[col]; v1 += row[col + 1]; }
                row[col] = v0; row[col + 1] = v1;
            }
        }
    }
}

// ================= fallback SGEMM (head only) =================
__global__ void __launch_bounds__(256) gemm_kernel(
    const float* __restrict__ A, const float* __restrict__ B, float* __restrict__ C,
    int M, int N, int K,
    const float* __restrict__ bias, int flags)
{
    __shared__ __align__(16) float As[8][128];
    __shared__ __align__(16) float Bs[8][128];
    int tid = threadIdx.x;
    int m0 = blockIdx.y * 128;
    int n0 = blockIdx.x * 128;
    int tx = tid & 15, ty = tid >> 4;
    float acc[8][8];
#pragma unroll
    for (int i = 0; i < 8; i++)
#pragma unroll
        for (int j = 0; j < 8; j++) acc[i][j] = 0.f;
    for (int k0 = 0; k0 < K; k0 += 8) {
#pragma unroll
        for (int i = 0; i < 4; i++) {
            int l = tid + i * 256;
            int mm = l >> 3, kk = l & 7;
            int gk = k0 + kk, gm = m0 + mm;
            As[kk][mm] = (gk < K && gm < M) ? A[(long long)gm * K + gk] : 0.f;
        }
#pragma unroll
        for (int i = 0; i < 4; i++) {
            int l = tid + i * 256;
            int kk = l >> 7, nn = l & 127;
            int gk = k0 + kk, gn = n0 + nn;
            Bs[kk][nn] = (gk < K && gn < N) ? B[(long long)gk * N + gn] : 0.f;
        }
        __syncthreads();
#pragma unroll
        for (int k = 0; k < 8; k++) {
            float4 a0 = *(const float4*)&As[k][ty * 4];
            float4 a1 = *(const float4*)&As[k][ty * 4 + 64];
            float4 b0 = *(const float4*)&Bs[k][tx * 4];
            float4 b1 = *(const float4*)&Bs[k][tx * 4 + 64];
            float af[8] = {a0.x, a0.y, a0.z, a0.w, a1.x, a1.y, a1.z, a1.w};
            float bf_[8] = {b0.x, b0.y, b0.z, b0.w, b1.x, b1.y, b1.z, b1.w};
#pragma unroll
            for (int i = 0; i < 8; i++)
#pragma unroll
                for (int j = 0; j < 8; j++) acc[i][j] += af[i] * bf_[j];
        }
        __syncthreads();
    }
#pragma unroll
    for (int i = 0; i < 8; i++) {
        int gm = m0 + ((i < 4) ? ty * 4 + i : 64 + ty * 4 + (i - 4));
        if (gm >= M) continue;
        float* crow = C + (long long)gm * N;
#pragma unroll
        for (int j = 0; j < 8; j++) {
            int gn = n0 + ((j < 4) ? tx * 4 + j : 64 + tx * 4 + (j - 4));
            if (gn >= N) continue;
            float v = acc[i][j];
            if (flags & 1) v += bias[gn];
            crow[gn] = v;
        }
    }
}

// ================= layernorm: warp per row =================
__global__ void ln_kernel(const float* __restrict__ X, long long ldx,
                          float* __restrict__ Y, long long ldy,
                          const float* __restrict__ g, const float* __restrict__ b,
                          float* __restrict__ diag, int nrows)
{
    int w = blockIdx.x * (blockDim.x >> 5) + (threadIdx.x >> 5);
    int lane = threadIdx.x & 31;
    if (w >= nrows) return;
    const float4* x = (const float4*)(X + (long long)w * ldx);
    float4 v[6];
    float s1 = 0.f, s2 = 0.f;
#pragma unroll
    for (int i = 0; i < 6; i++) {
        v[i] = x[lane + 32 * i];
        s1 += v[i].x + v[i].y + v[i].z + v[i].w;
        s2 += v[i].x * v[i].x + v[i].y * v[i].y + v[i].z * v[i].z + v[i].w * v[i].w;
    }
#pragma unroll
    for (int o = 16; o > 0; o >>= 1) {
        s1 += __shfl_xor_sync(0xffffffffu, s1, o);
        s2 += __shfl_xor_sync(0xffffffffu, s2, o);
    }
    float mu  = s1 * (1.0f / 768.0f);
    float var = s2 * (1.0f / 768.0f) - mu * mu;
    float inv = rsqrtf(var + 1e-5f);
    const float4* g4 = (const float4*)g;
    const float4* b4 = (const float4*)b;
    float4* y4 = (float4*)(Y + (long long)w * ldy);
    float d = 0.f;
#pragma unroll
    for (int i = 0; i < 6; i++) {
        float4 gv = g4[lane + 32 * i], bv = b4[lane + 32 * i], o;
        o.x = (v[i].x - mu) * inv * gv.x + bv.x;
        o.y = (v[i].y - mu) * inv * gv.y + bv.y;
        o.z = (v[i].z - mu) * inv * gv.z + bv.z;
        o.w = (v[i].w - mu) * inv * gv.w + bv.w;
        d += o.x * o.x + o.y * o.y + o.z * o.z + o.w * o.w;
        y4[lane + 32 * i] = o;
    }
    if (diag) {
#pragma unroll
        for (int o = 16; o > 0; o >>= 1) d += __shfl_xor_sync(0xffffffffu, d, o);
        if (lane == 0) diag[w] = 0.5f * SCAL * SCAL * d;
    }
}

// ================= performer helpers =================
__global__ void lg_rowmax_kernel(float* __restrict__ lg, const float* __restrict__ diag,
                                 float* __restrict__ qmax)
{
    int row = blockIdx.x;
    int tid = threadIdx.x;
    long long idx = (long long)row * MFEAT + tid;
    float v = lg[idx] * SCAL - diag[row];
    lg[idx] = v;
    __shared__ float red[8];
    float m = v;
#pragma unroll
    for (int o = 16; o > 0; o >>= 1) m = fmaxf(m, __shfl_down_sync(0xffffffffu, m, o));
    int w = tid >> 5, lane = tid & 31;
    if (lane == 0) red[w] = m;
    __syncthreads();
    if (tid == 0) {
        float a = red[0];
        for (int i = 1; i < 8; i++) a = fmaxf(a, red[i]);
        qmax[row] = a;
    }
}

__global__ void gmax_kernel(const float* __restrict__ qmax, float* __restrict__ gmax)
{
    int tid = threadIdx.x;
    float m = -1e30f;
    for (int i = tid; i < ROWS; i += 256) m = fmaxf(m, qmax[i]);
    __shared__ float red[8];
#pragma unroll
    for (int o = 16; o > 0; o >>= 1) m = fmaxf(m, __shfl_down_sync(0xffffffffu, m, o));
    int w = tid >> 5, lane = tid & 31;
    if (lane == 0) red[w] = m;
    __syncthreads();
    if (tid == 0) {
        float a = red[0];
        for (int i = 1; i < 8; i++) a = fmaxf(a, red[i]);
        gmax[0] = a;
    }
}

__global__ void feat_kernel(const float* __restrict__ lg, const float* __restrict__ qmax,
                            const float* __restrict__ gmax,
                            float* __restrict__ qf, float* __restrict__ kfT)
{
    long long i = (long long)blockIdx.x * 256 + threadIdx.x;
    if (i >= (long long)ROWS * MFEAT) return;
    int tg = (int)(i >> 8);
    int m = (int)(i & 255);
    int b = tg / NTOK;
    int t = tg - b * NTOK;
    float v = lg[i];
    qf[i] = expf(v - qmax[tg]) * MSCL + FEPS;
    kfT[((long long)(b * MFEAT + m)) * KPAD + t] = expf(v - gmax[0]) * MSCL + FEPS;
}

__global__ void ksum_kernel(const float* __restrict__ kfT, float* __restrict__ ksum)
{
    int w = (blockIdx.x * blockDim.x + threadIdx.x) >> 5;
    int lane = threadIdx.x & 31;
    if (w >= BSZ * MFEAT) return;
    const float* p = kfT + (long long)w * KPAD;
    float s = 0.f;
#pragma unroll
    for (int t = lane; t < KPAD; t += 32) s += p[t];
#pragma unroll
    for (int o = 16; o > 0; o >>= 1) s += __shfl_down_sync(0xffffffffu, s, o);
    if (lane == 0) ksum[w] = s;
}

__global__ void den_kernel(const float* __restrict__ qf, const float* __restrict__ ksum,
                           float* __restrict__ den)
{
    int warp = (blockIdx.x * blockDim.x + threadIdx.x) >> 5;
    int lane = threadIdx.x & 31;
    if (warp >= ROWS) return;
    int b = warp / NTOK;
    const float* q  = qf + (long long)warp * MFEAT;
    const float* ks = ksum + b * MFEAT;
    float s = 0.f;
#pragma unroll
    for (int m = lane; m < MFEAT; m += 32) s += q[m] * ks[m];
#pragma unroll
    for (int o = 16; o > 0; o >>= 1) s += __shfl_down_sync(0xffffffffu, s, o);
    if (lane == 0) den[warp] = s;
}

// ================= transpose (tiled) =================
__global__ void transpose_tiled(const float* __restrict__ in, float* __restrict__ out,
                                int R, int Ccol, int ldo, long long sin, long long sout)
{
    __shared__ float t[32][33];
    const float* ip = in + (long long)blockIdx.z * sin;
    float* op = out + (long long)blockIdx.z * sout;
    int c0 = blockIdx.x * 32, r0 = blockIdx.y * 32;
    int tx = threadIdx.x, ty = threadIdx.y;
#pragma unroll
    for (int k = 0; k < 4; k++) {
        int r = r0 + ty + 8 * k;
        if (r < R && c0 + tx < Ccol)
            t[ty + 8 * k][tx] = ip[(long long)r * Ccol + c0 + tx];
    }
    __syncthreads();
#pragma unroll
    for (int k = 0; k < 4; k++) {
        int c = c0 + ty + 8 * k;
        int r = r0 + tx;
        if (c < Ccol && r < R)
            op[(long long)c * ldo + r] = t[tx][ty + 8 * k];
    }
}

// ================= misc elementwise =================
__global__ void im2col_kernel(const float* __restrict__ x, float* __restrict__ pt)
{
    long long i = (long long)blockIdx.x * 256 + threadIdx.x;
    if (i >= (long long)BSZ * NPATCH * 768) return;
    int kidx = (int)(i % 768);
    int p    = (int)(i / 768);
    int pj = kidx & 15, pi = (kidx >> 4) & 15, c = kidx >> 8;
    int gj = p % 14;
    int t  = p / 14;
    int gi = t % 14;
    int b  = t / 14;
    pt[i] = x[(((long long)(b * 3 + c) * 224 + gi * 16 + pi) * 224) + gj * 16 + pj];
}

__global__ void assemble_kernel(const float* __restrict__ tok, const float* __restrict__ cls_tok,
                                const float* __restrict__ pos, float* __restrict__ h)
{
    long long i = (long long)blockIdx.x * 256 + threadIdx.x;
    if (i >= (long long)ROWS * EDIM) return;
    int e = (int)(i % EDIM);
    int t = (int)(i / EDIM);
    int n = t % NTOK;
    int b = t / NTOK;
    float v = (n == 0) ? cls_tok[e] : tok[(long long)(b * NPATCH + n - 1) * EDIM + e];
    h[i] = v + pos[(long long)n * EDIM + e];
}

__global__ void combine_kernel(const float* __restrict__ part, const float* __restrict__ b2,
                               float* __restrict__ h)
{
    long long i = (long long)blockIdx.x * 256 + threadIdx.x;
    if (i >= (long long)ROWS * EDIM) return;
    int e = (int)(i % EDIM);
    h[i] += part[i] + part[(long long)ROWS * EDIM + i] + b2[e];
}

// ================= host =================
static inline float* sym(const void* s)
{
    void* p = nullptr;
    cudaGetSymbolAddress(&p, s);
    return (float*)p;
}

extern "C" void kernel_launch(void* const* d_in, const int* in_sizes, int n_in,
                              void* d_out, int out_size)
{
    const float* x       = (const float*)d_in[0];
    const float* cls_tok = (const float*)d_in[1];
    const float* pos_emb = (const float*)d_in[2];
    const float* patch_w = (const float*)d_in[3];
    const float* patch_b = (const float*)d_in[4];
    const float* ln1_g   = (const float*)d_in[5];
    const float* ln1_b   = (const float*)d_in[6];
    const float* proj    = (const float*)d_in[7];
    const float* ln2_g   = (const float*)d_in[8];
    const float* ln2_b   = (const float*)d_in[9];
    const float* w1      = (const float*)d_in[10];
    const float* b1      = (const float*)d_in[11];
    const float* w2      = (const float*)d_in[12];
    const float* b2      = (const float*)d_in[13];
    const float* lnf_g   = (const float*)d_in[14];
    const float* lnf_b   = (const float*)d_in[15];
    const float* head_w  = (const float*)d_in[16];
    const float* head_b  = (const float*)d_in[17];
    float* out = (float*)d_out;

    float* h    = sym(g_h);
    float* y    = sym(g_y);
    float* tmp  = sym(g_tmp);
    float* lg   = sym(g_lg);
    float* qf   = sym(g_qf);
    float* kfT  = sym(g_kfT);
    float* yT   = sym(g_yT);
    float* kvT  = sym(g_kvT);
    float* part = sym(g_part);
    float* diag = sym(g_diag);
    float* qmax = sym(g_qmax);
    float* den  = sym(g_den);
    float* ksum = sym(g_ksum);
    float* gmax = sym(g_gmax);
    float* clsb = sym(g_cls);
    float* w1T  = sym(g_w1T);
    float* w2T  = sym(g_w2T);

    float* pt  = tmp;             // [3136,768] im2col
    float* tok = tmp + 5000000;   // [3136,768] patch-embed out

    // --- weight transposes (w1T[l]: [3072,768], w2T[l]: [768,3072]) ---
    {
        dim3 blk(32, 8);
        transpose_tiled<<<dim3(96, 24, NLAYER), blk>>>(w1, w1T, EDIM, FDIM, EDIM,
            (long long)EDIM * FDIM, (long long)EDIM * FDIM);
        transpose_tiled<<<dim3(24, 96, NLAYER), blk>>>(w2, w2T, FDIM, EDIM, FDIM,
            (long long)EDIM * FDIM, (long long)EDIM * FDIM);
    }

    // --- patch embedding ---
    {
        long long tot = (long long)BSZ * NPATCH * 768;
        im2col_kernel<<<(unsigned)((tot + 255) / 256), 256>>>(x, pt);
        mma_gemm<<<dim3(6, 49, 1), 256>>>(pt, patch_w, tok,
            BSZ * NPATCH, 768, 768, EDIM, 0, 0, 0, 0, 0, 768,
            patch_b, nullptr, 0, 1);
        long long ht = (long long)ROWS * EDIM;
        assemble_kernel<<<(unsigned)((ht + 255) / 256), 256>>>(tok, cls_tok, pos_emb, h);
    }

    for (int l = 0; l < NLAYER; l++) {
        const float* prj = proj + (long long)l * MFEAT * EDIM;
        // LN1 + diag
        ln_kernel<<<(ROWS + 7) / 8, 256>>>(h, EDIM, y, EDIM,
            ln1_g + l * EDIM, ln1_b + l * EDIM, diag, ROWS);
        // logits = y @ proj^T (raw)
        mma_gemm<<<dim3(2, 50, 1), 256>>>(y, prj, lg,
            ROWS, EDIM, EDIM, MFEAT, 0, 0, 0, 0, 0, EDIM,
            nullptr, nullptr, 0, 0);
        lg_rowmax_kernel<<<ROWS, 256>>>(lg, diag, qmax);
        gmax_kernel<<<1, 256>>>(qmax, gmax);
        feat_kernel<<<(ROWS * MFEAT + 255) / 256, 256>>>(lg, qmax, gmax, qf, kfT);
        ksum_kernel<<<(BSZ * MFEAT * 32 + 255) / 256, 256>>>(kfT, ksum);
        // yT[b][e][t] (zero-padded t>=197)
        transpose_tiled<<<dim3(24, 7, BSZ), dim3(32, 8)>>>(y, yT, NTOK, EDIM, KPAD,
            (long long)NTOK * EDIM, (long long)EDIM * KPAD);
        // kvT[b] = yT[b] @ kfT[b]^T : [768,256], K=224
        mma_gemm<<<dim3(2, 12, BSZ), 256>>>(yT, kfT, kvT,
            EDIM, KPAD, KPAD, MFEAT,
            (long long)EDIM * KPAD, (long long)MFEAT * KPAD, (long long)EDIM * MFEAT,
            0, 0, KPAD, nullptr, nullptr, 0, 0);
        den_kernel<<<(ROWS + 7) / 8, 256>>>(qf, ksum, den);
        // h += (qf @ kvT^T) / den
        mma_gemm<<<dim3(6, 4, BSZ), 256>>>(qf, kvT, h,
            NTOK, MFEAT, MFEAT, EDIM,
            (long long)NTOK * MFEAT, (long long)EDIM * MFEAT, (long long)NTOK * EDIM,
            0, 0, MFEAT, nullptr, den, NTOK, 4 | 8);
        // LN2
        ln_kernel<<<(ROWS + 7) / 8, 256>>>(h, EDIM, y, EDIM,
            ln2_g + l * EDIM, ln2_b + l * EDIM, nullptr, ROWS);
        // hid = gelu(y @ w1 + b1)
        mma_gemm<<<dim3(24, 50, 1), 256>>>(y, w1T + (long long)l * EDIM * FDIM, tmp,
            ROWS, EDIM, EDIM, FDIM, 0, 0, 0, 0, 0, EDIM,
            b1 + l * FDIM, nullptr, 0, 1 | 2);
        // part[z] = hid[:, zK:] @ w2T[:, zK:]^T   (split-K over 2)
        mma_gemm<<<dim3(6, 50, 2), 256>>>(tmp, w2T + (long long)l * EDIM * FDIM, part,
            ROWS, FDIM, FDIM, EDIM, 0, 0, (long long)ROWS * EDIM,
            0, FDIM / 2, FDIM / 2, nullptr, nullptr, 0, 0);
        combine_kernel<<<(ROWS * EDIM + 255) / 256, 256>>>(part, b2 + l * EDIM, h);
    }

    // final LN on CLS tokens + head
    ln_kernel<<<2, 256>>>(h, (long long)NTOK * EDIM, clsb, EDIM, lnf_g, lnf_b, nullptr, BSZ);
    {
        dim3 grid(8, 1, 1);
        gemm_kernel<<<grid, 256>>>(clsb, head_w, out,
            BSZ, NC, EDIM, head_b, 1);
    }
}

// round 17
// speedup vs baseline: 2.0548x; 1.0347x over previous
#include <cuda_runtime.h>
#include <cuda_bf16.h>
#include <math.h>
#include <stdint.h>

// ---------------- problem constants ----------------
#define EDIM   768
#define NTOK   197
#define BSZ    16
#define ROWS   (BSZ*NTOK)      // 3152
#define MFEAT  256
#define FDIM   3072
#define NPATCH 196
#define NC     1000
#define NLAYER 12
#define KPAD   224             // 197 padded to mult of 32

#define SCAL  0.18995897f      // 768^{-1/4}
#define MSCL  0.0625f          // 256^{-1/2}
#define FEPS  1e-4f

// ---------------- scratch (device globals; allocation-free) ----------------
__device__ float g_h   [ROWS*EDIM];
__device__ float g_y   [ROWS*EDIM];
__device__ float g_tmp [ROWS*FDIM];          // MLP hidden; im2col+tok at start
__device__ float g_lg  [ROWS*MFEAT];
__device__ float g_qf  [ROWS*MFEAT];
__device__ float g_kfT [BSZ*MFEAT*KPAD];     // [b][m][t] zero-padded t>=197
__device__ float g_yT  [BSZ*EDIM*KPAD];      // [b][e][t] zero-padded
__device__ float g_kvT [BSZ*EDIM*MFEAT];     // [b][e][m]
__device__ float g_diag[ROWS];
__device__ float g_qmax[ROWS];
__device__ float g_den [ROWS];
__device__ float g_ksum[BSZ*MFEAT];
__device__ float g_gmax[1];
__device__ float g_cls [BSZ*EDIM];
__device__ float g_w1T [NLAYER*EDIM*FDIM];   // [l][f][e]
__device__ float g_w2T [NLAYER*EDIM*FDIM];   // [l][e][f]

// ================= bf16-split mma.sync GEMM =================
// C[M, N=grid.x*128] = A[M,klen] @ B[N,klen]^T   (both fp32 K-major)
// 2-term bf16 split, 3 products: fp32-like accuracy (~1e-5).
// CTA tile: 64(M) x 128(N); 256 threads, 8 warps in 2x4 grid (each 32x32).
// __launch_bounds__(256,2) -> 2 CTAs/SM for cross-CTA latency hiding.
// B fragments loaded with ldmatrix.x4 (two nt tiles per instruction).
// flags: 1=+bias[n]  2=gelu  4=accumulate into C  8=divide by rowdiv[z*sdiv+m]

#define SPITCH 40   // smem row pitch in halfs (80 bytes): conflict-free for ldmatrix

__device__ __forceinline__ void mma_bf16(float* c, const uint32_t* a, const uint32_t* b)
{
    asm volatile(
        "mma.sync.aligned.m16n8k16.row.col.f32.bf16.bf16.f32 "
        "{%0,%1,%2,%3}, {%4,%5,%6,%7}, {%8,%9}, {%0,%1,%2,%3};"
        : "+f"(c[0]), "+f"(c[1]), "+f"(c[2]), "+f"(c[3])
        : "r"(a[0]), "r"(a[1]), "r"(a[2]), "r"(a[3]), "r"(b[0]), "r"(b[1]));
}

__device__ __forceinline__ uint32_t smem_addr(const void* p)
{
    uint32_t a;
    asm("{ .reg .u64 t; cvta.to.shared.u64 t, %1; cvt.u32.u64 %0, t; }"
        : "=r"(a) : "l"(p));
    return a;
}

__device__ __forceinline__ void ldsm_x4(uint32_t* r, uint32_t addr)
{
    asm volatile("ldmatrix.sync.aligned.m8n8.x4.shared.b16 {%0,%1,%2,%3}, [%4];"
                 : "=r"(r[0]), "=r"(r[1]), "=r"(r[2]), "=r"(r[3]) : "r"(addr));
}

// split float4 -> packed hi(2xuint) and lo(2xuint) bf16x2
__device__ __forceinline__ void split_pack(float4 v, uint2& hi, uint2& lo)
{
    __nv_bfloat16 hx = __float2bfloat16(v.x);
    __nv_bfloat16 hy = __float2bfloat16(v.y);
    __nv_bfloat16 hz = __float2bfloat16(v.z);
    __nv_bfloat16 hw = __float2bfloat16(v.w);
    __nv_bfloat16 lx = __float2bfloat16(v.x - __bfloat162float(hx));
    __nv_bfloat16 ly = __float2bfloat16(v.y - __bfloat162float(hy));
    __nv_bfloat16 lz = __float2bfloat16(v.z - __bfloat162float(hz));
    __nv_bfloat16 lw = __float2bfloat16(v.w - __bfloat162float(hw));
    __nv_bfloat162 h0 = __halves2bfloat162(hx, hy);
    __nv_bfloat162 h1 = __halves2bfloat162(hz, hw);
    __nv_bfloat162 l0 = __halves2bfloat162(lx, ly);
    __nv_bfloat162 l1 = __halves2bfloat162(lz, lw);
    hi.x = *(uint32_t*)&h0; hi.y = *(uint32_t*)&h1;
    lo.x = *(uint32_t*)&l0; lo.y = *(uint32_t*)&l1;
}

__global__ void __launch_bounds__(256, 2) mma_gemm(
    const float* __restrict__ A, const float* __restrict__ B, float* __restrict__ C,
    int M, int ldA, int ldB, int ldC,
    long long sA, long long sB, long long sC,
    int kstart, int kzs, int klen,
    const float* __restrict__ bias, const float* __restrict__ rowdiv, int sdiv, int flags)
{
    __shared__ __align__(16) __nv_bfloat16 Ah[64 * SPITCH];
    __shared__ __align__(16) __nv_bfloat16 Al[64 * SPITCH];
    __shared__ __align__(16) __nv_bfloat16 Bh[128 * SPITCH];
    __shared__ __align__(16) __nv_bfloat16 Bl[128 * SPITCH];

    int tid = threadIdx.x;
    int wid = tid >> 5, lane = tid & 31;
    int m0 = blockIdx.y * 64, n0 = blockIdx.x * 128, z = blockIdx.z;
    int warpM = wid >> 2;          // 0..1 -> 32 rows each
    int warpN = wid & 3;           // 0..3 -> 32 cols each
    int qr = lane >> 2;            // group row 0..7
    int qc = (lane & 3) * 2;       // k pair base

    // ldmatrix per-lane byte offsets
    uint32_t AhB = smem_addr(Ah), AlB = smem_addr(Al);
    uint32_t BhB = smem_addr(Bh), BlB = smem_addr(Bl);
    uint32_t aoff = (uint32_t)(((warpM * 32 + (lane & 15)) * SPITCH + ((lane >> 4) << 3)) * 2);
    // B x4 offsets: lanes 0-15 -> nt tile, lanes 16-31 -> nt+1 tile; khalf = (lane>>3)&1
    uint32_t boff4 = (uint32_t)(((warpN * 32 + (lane & 7) + ((lane >> 4) << 3)) * SPITCH
                                 + (((lane >> 3) & 1) << 3)) * 2);

    const float* Ab = A + (long long)z * sA + kstart + (long long)z * kzs;
    const float* Bb = B + (long long)z * sB + kstart + (long long)z * kzs;

    float acc[2][4][4];
#pragma unroll
    for (int i = 0; i < 2; i++)
#pragma unroll
        for (int j = 0; j < 4; j++)
#pragma unroll
            for (int r = 0; r < 4; r++) acc[i][j][r] = 0.f;

    int kt_n = klen >> 5;

    // prefetch tile 0 into regs (A: 2 float4/thread over 64 rows, B: 4 over 128)
    float4 av[2], bv[4];
#pragma unroll
    for (int i = 0; i < 2; i++) {
        int idx = tid + (i << 8);
        int r = idx >> 3, c4 = idx & 7;
        int gm = m0 + r;
        av[i] = (gm < M) ? *(const float4*)(Ab + (long long)gm * ldA + (c4 << 2))
                         : make_float4(0.f, 0.f, 0.f, 0.f);
    }
#pragma unroll
    for (int i = 0; i < 4; i++) {
        int idx = tid + (i << 8);
        int r = idx >> 3, c4 = idx & 7;
        bv[i] = *(const float4*)(Bb + (long long)(n0 + r) * ldB + (c4 << 2));
    }

    for (int kt = 0; kt < kt_n; kt++) {
        __syncthreads();   // previous compute done; smem reusable
        // convert + store current tile
#pragma unroll
        for (int i = 0; i < 2; i++) {
            int idx = tid + (i << 8);
            int r = idx >> 3, c4 = idx & 7;
            int ho = r * SPITCH + c4 * 4;
            uint2 hi, lo;
            split_pack(av[i], hi, lo);
            *(uint2*)&Ah[ho] = hi; *(uint2*)&Al[ho] = lo;
        }
#pragma unroll
        for (int i = 0; i < 4; i++) {
            int idx = tid + (i << 8);
            int r = idx >> 3, c4 = idx & 7;
            int ho = r * SPITCH + c4 * 4;
            uint2 hi, lo;
            split_pack(bv[i], hi, lo);
            *(uint2*)&Bh[ho] = hi; *(uint2*)&Bl[ho] = lo;
        }
        __syncthreads();
        // prefetch next tile
        if (kt + 1 < kt_n) {
            long long ko = ((long long)(kt + 1) << 5);
#pragma unroll
            for (int i = 0; i < 2; i++) {
                int idx = tid + (i << 8);
                int r = idx >> 3, c4 = idx & 7;
                int gm = m0 + r;
                av[i] = (gm < M) ? *(const float4*)(Ab + (long long)gm * ldA + ko + (c4 << 2))
                                 : make_float4(0.f, 0.f, 0.f, 0.f);
            }
#pragma unroll
            for (int i = 0; i < 4; i++) {
                int idx = tid + (i << 8);
                int r = idx >> 3, c4 = idx & 7;
                bv[i] = *(const float4*)(Bb + (long long)(n0 + r) * ldB + ko + (c4 << 2));
            }
        }
        // compute 32-deep K slab
#pragma unroll
        for (int ks = 0; ks < 2; ks++) {
            uint32_t kbyte = (uint32_t)(ks * 16 * 2);
            uint32_t bhf[4][2], blf[4][2];
#pragma unroll
            for (int np = 0; np < 2; np++) {
                uint32_t bo = boff4 + (uint32_t)(np * 16 * SPITCH * 2) + kbyte;
                uint32_t r4[4];
                ldsm_x4(r4, BhB + bo);
                bhf[np * 2][0] = r4[0]; bhf[np * 2][1] = r4[1];
                bhf[np * 2 + 1][0] = r4[2]; bhf[np * 2 + 1][1] = r4[3];
                ldsm_x4(r4, BlB + bo);
                blf[np * 2][0] = r4[0]; blf[np * 2][1] = r4[1];
                blf[np * 2 + 1][0] = r4[2]; blf[np * 2 + 1][1] = r4[3];
            }
#pragma unroll
            for (int mt = 0; mt < 2; mt++) {
                uint32_t ao = aoff + (uint32_t)(mt * 16 * SPITCH * 2) + kbyte;
                uint32_t ahf[4], alf[4];
                ldsm_x4(ahf, AhB + ao);
                ldsm_x4(alf, AlB + ao);
#pragma unroll
                for (int nt = 0; nt < 4; nt++) {
                    mma_bf16(acc[mt][nt], ahf, bhf[nt]);
                    mma_bf16(acc[mt][nt], ahf, blf[nt]);
                    mma_bf16(acc[mt][nt], alf, bhf[nt]);
                }
            }
        }
    }

    // ---- epilogue ----
#pragma unroll
    for (int mt = 0; mt < 2; mt++) {
        int r0 = m0 + warpM * 32 + mt * 16 + qr;
        int r1 = r0 + 8;
        bool ok0 = r0 < M, ok1 = r1 < M;
        float dv0 = 1.f, dv1 = 1.f;
        if (flags & 8) {
            if (ok0) dv0 = 1.f / rowdiv[(long long)z * sdiv + r0];
            if (ok1) dv1 = 1.f / rowdiv[(long long)z * sdiv + r1];
        }
        float* row0 = C + (long long)z * sC + (long long)r0 * ldC;
        float* row1 = C + (long long)z * sC + (long long)r1 * ldC;
#pragma unroll
        for (int nt = 0; nt < 4; nt++) {
            int col = n0 + warpN * 32 + nt * 8 + qc;
            float b0 = 0.f, b1 = 0.f;
            if (flags & 1) { b0 = bias[col]; b1 = bias[col + 1]; }
#pragma unroll
            for (int half = 0; half < 2; half++) {
                bool ok = half ? ok1 : ok0;
                if (!ok) continue;
                float dv = half ? dv1 : dv0;
                float* row = half ? row1 : row0;
                float v0 = acc[mt][nt][half * 2 + 0];
                float v1 = acc[mt][nt][half * 2 + 1];
                v0 += b0; v1 += b1;
                if (flags & 2) {
                    v0 = 0.5f * v0 * (1.f + erff(v0 * 0.70710678118654752f));
                    v1 = 0.5f * v1 * (1.f + erff(v1 * 0.70710678118654752f));
                }
                if (flags & 8) { v0 *= dv; v1 *= dv; }
                if (flags & 4) { v0 += row[col]; v1 += row[col + 1]; }
                row[col] = v0; row[col + 1] = v1;
            }
        }
    }
}

// ================= fallback SGEMM (head only) =================
__global__ void __launch_bounds__(256) gemm_kernel(
    const float* __restrict__ A, const float* __restrict__ B, float* __restrict__ C,
    int M, int N, int K,
    const float* __restrict__ bias, int flags)
{
    __shared__ __align__(16) float As[8][128];
    __shared__ __align__(16) float Bs[8][128];
    int tid = threadIdx.x;
    int m0 = blockIdx.y * 128;
    int n0 = blockIdx.x * 128;
    int tx = tid & 15, ty = tid >> 4;
    float acc[8][8];
#pragma unroll
    for (int i = 0; i < 8; i++)
#pragma unroll
        for (int j = 0; j < 8; j++) acc[i][j] = 0.f;
    for (int k0 = 0; k0 < K; k0 += 8) {
#pragma unroll
        for (int i = 0; i < 4; i++) {
            int l = tid + i * 256;
            int mm = l >> 3, kk = l & 7;
            int gk = k0 + kk, gm = m0 + mm;
            As[kk][mm] = (gk < K && gm < M) ? A[(long long)gm * K + gk] : 0.f;
        }
#pragma unroll
        for (int i = 0; i < 4; i++) {
            int l = tid + i * 256;
            int kk = l >> 7, nn = l & 127;
            int gk = k0 + kk, gn = n0 + nn;
            Bs[kk][nn] = (gk < K && gn < N) ? B[(long long)gk * N + gn] : 0.f;
        }
        __syncthreads();
#pragma unroll
        for (int k = 0; k < 8; k++) {
            float4 a0 = *(const float4*)&As[k][ty * 4];
            float4 a1 = *(const float4*)&As[k][ty * 4 + 64];
            float4 b0 = *(const float4*)&Bs[k][tx * 4];
            float4 b1 = *(const float4*)&Bs[k][tx * 4 + 64];
            float af[8] = {a0.x, a0.y, a0.z, a0.w, a1.x, a1.y, a1.z, a1.w};
            float bf_[8] = {b0.x, b0.y, b0.z, b0.w, b1.x, b1.y, b1.z, b1.w};
#pragma unroll
            for (int i = 0; i < 8; i++)
#pragma unroll
                for (int j = 0; j < 8; j++) acc[i][j] += af[i] * bf_[j];
        }
        __syncthreads();
    }
#pragma unroll
    for (int i = 0; i < 8; i++) {
        int gm = m0 + ((i < 4) ? ty * 4 + i : 64 + ty * 4 + (i - 4));
        if (gm >= M) continue;
        float* crow = C + (long long)gm * N;
#pragma unroll
        for (int j = 0; j < 8; j++) {
            int gn = n0 + ((j < 4) ? tx * 4 + j : 64 + tx * 4 + (j - 4));
            if (gn >= N) continue;
            float v = acc[i][j];
            if (flags & 1) v += bias[gn];
            crow[gn] = v;
        }
    }
}

// ================= layernorm: warp per row =================
__global__ void ln_kernel(const float* __restrict__ X, long long ldx,
                          float* __restrict__ Y, long long ldy,
                          const float* __restrict__ g, const float* __restrict__ b,
                          float* __restrict__ diag, int nrows)
{
    int w = blockIdx.x * (blockDim.x >> 5) + (threadIdx.x >> 5);
    int lane = threadIdx.x & 31;
    if (w >= nrows) return;
    const float4* x = (const float4*)(X + (long long)w * ldx);
    float4 v[6];
    float s1 = 0.f, s2 = 0.f;
#pragma unroll
    for (int i = 0; i < 6; i++) {
        v[i] = x[lane + 32 * i];
        s1 += v[i].x + v[i].y + v[i].z + v[i].w;
        s2 += v[i].x * v[i].x + v[i].y * v[i].y + v[i].z * v[i].z + v[i].w * v[i].w;
    }
#pragma unroll
    for (int o = 16; o > 0; o >>= 1) {
        s1 += __shfl_xor_sync(0xffffffffu, s1, o);
        s2 += __shfl_xor_sync(0xffffffffu, s2, o);
    }
    float mu  = s1 * (1.0f / 768.0f);
    float var = s2 * (1.0f / 768.0f) - mu * mu;
    float inv = rsqrtf(var + 1e-5f);
    const float4* g4 = (const float4*)g;
    const float4* b4 = (const float4*)b;
    float4* y4 = (float4*)(Y + (long long)w * ldy);
    float d = 0.f;
#pragma unroll
    for (int i = 0; i < 6; i++) {
        float4 gv = g4[lane + 32 * i], bv = b4[lane + 32 * i], o;
        o.x = (v[i].x - mu) * inv * gv.x + bv.x;
        o.y = (v[i].y - mu) * inv * gv.y + bv.y;
        o.z = (v[i].z - mu) * inv * gv.z + bv.z;
        o.w = (v[i].w - mu) * inv * gv.w + bv.w;
        d += o.x * o.x + o.y * o.y + o.z * o.z + o.w * o.w;
        y4[lane + 32 * i] = o;
    }
    if (diag) {
#pragma unroll
        for (int o = 16; o > 0; o >>= 1) d += __shfl_xor_sync(0xffffffffu, d, o);
        if (lane == 0) diag[w] = 0.5f * SCAL * SCAL * d;
    }
}

// ================= performer helpers =================
__global__ void lg_rowmax_kernel(float* __restrict__ lg, const float* __restrict__ diag,
                                 float* __restrict__ qmax)
{
    int row = blockIdx.x;
    int tid = threadIdx.x;
    long long idx = (long long)row * MFEAT + tid;
    float v = lg[idx] * SCAL - diag[row];
    lg[idx] = v;
    __shared__ float red[8];
    float m = v;
#pragma unroll
    for (int o = 16; o > 0; o >>= 1) m = fmaxf(m, __shfl_down_sync(0xffffffffu, m, o));
    int w = tid >> 5, lane = tid & 31;
    if (lane == 0) red[w] = m;
    __syncthreads();
    if (tid == 0) {
        float a = red[0];
        for (int i = 1; i < 8; i++) a = fmaxf(a, red[i]);
        qmax[row] = a;
    }
}

__global__ void gmax_kernel(const float* __restrict__ qmax, float* __restrict__ gmax)
{
    int tid = threadIdx.x;
    float m = -1e30f;
    for (int i = tid; i < ROWS; i += 256) m = fmaxf(m, qmax[i]);
    __shared__ float red[8];
#pragma unroll
    for (int o = 16; o > 0; o >>= 1) m = fmaxf(m, __shfl_down_sync(0xffffffffu, m, o));
    int w = tid >> 5, lane = tid & 31;
    if (lane == 0) red[w] = m;
    __syncthreads();
    if (tid == 0) {
        float a = red[0];
        for (int i = 1; i < 8; i++) a = fmaxf(a, red[i]);
        gmax[0] = a;
    }
}

__global__ void feat_kernel(const float* __restrict__ lg, const float* __restrict__ qmax,
                            const float* __restrict__ gmax,
                            float* __restrict__ qf, float* __restrict__ kfT)
{
    long long i = (long long)blockIdx.x * 256 + threadIdx.x;
    if (i >= (long long)ROWS * MFEAT) return;
    int tg = (int)(i >> 8);
    int m = (int)(i & 255);
    int b = tg / NTOK;
    int t = tg - b * NTOK;
    float v = lg[i];
    qf[i] = expf(v - qmax[tg]) * MSCL + FEPS;
    kfT[((long long)(b * MFEAT + m)) * KPAD + t] = expf(v - gmax[0]) * MSCL + FEPS;
}

__global__ void ksum_kernel(const float* __restrict__ kfT, float* __restrict__ ksum)
{
    int w = (blockIdx.x * blockDim.x + threadIdx.x) >> 5;
    int lane = threadIdx.x & 31;
    if (w >= BSZ * MFEAT) return;
    const float* p = kfT + (long long)w * KPAD;
    float s = 0.f;
#pragma unroll
    for (int t = lane; t < KPAD; t += 32) s += p[t];
#pragma unroll
    for (int o = 16; o > 0; o >>= 1) s += __shfl_down_sync(0xffffffffu, s, o);
    if (lane == 0) ksum[w] = s;
}

__global__ void den_kernel(const float* __restrict__ qf, const float* __restrict__ ksum,
                           float* __restrict__ den)
{
    int warp = (blockIdx.x * blockDim.x + threadIdx.x) >> 5;
    int lane = threadIdx.x & 31;
    if (warp >= ROWS) return;
    int b = warp / NTOK;
    const float* q  = qf + (long long)warp * MFEAT;
    const float* ks = ksum + b * MFEAT;
    float s = 0.f;
#pragma unroll
    for (int m = lane; m < MFEAT; m += 32) s += q[m] * ks[m];
#pragma unroll
    for (int o = 16; o > 0; o >>= 1) s += __shfl_down_sync(0xffffffffu, s, o);
    if (lane == 0) den[warp] = s;
}

// ================= transpose (tiled) =================
__global__ void transpose_tiled(const float* __restrict__ in, float* __restrict__ out,
                                int R, int Ccol, int ldo, long long sin, long long sout)
{
    __shared__ float t[32][33];
    const float* ip = in + (long long)blockIdx.z * sin;
    float* op = out + (long long)blockIdx.z * sout;
    int c0 = blockIdx.x * 32, r0 = blockIdx.y * 32;
    int tx = threadIdx.x, ty = threadIdx.y;
#pragma unroll
    for (int k = 0; k < 4; k++) {
        int r = r0 + ty + 8 * k;
        if (r < R && c0 + tx < Ccol)
            t[ty + 8 * k][tx] = ip[(long long)r * Ccol + c0 + tx];
    }
    __syncthreads();
#pragma unroll
    for (int k = 0; k < 4; k++) {
        int c = c0 + ty + 8 * k;
        int r = r0 + tx;
        if (c < Ccol && r < R)
            op[(long long)c * ldo + r] = t[tx][ty + 8 * k];
    }
}

// ================= misc elementwise =================
__global__ void im2col_kernel(const float* __restrict__ x, float* __restrict__ pt)
{
    long long i = (long long)blockIdx.x * 256 + threadIdx.x;
    if (i >= (long long)BSZ * NPATCH * 768) return;
    int kidx = (int)(i % 768);
    int p    = (int)(i / 768);
    int pj = kidx & 15, pi = (kidx >> 4) & 15, c = kidx >> 8;
    int gj = p % 14;
    int t  = p / 14;
    int gi = t % 14;
    int b  = t / 14;
    pt[i] = x[(((long long)(b * 3 + c) * 224 + gi * 16 + pi) * 224) + gj * 16 + pj];
}

__global__ void assemble_kernel(const float* __restrict__ tok, const float* __restrict__ cls_tok,
                                const float* __restrict__ pos, float* __restrict__ h)
{
    long long i = (long long)blockIdx.x * 256 + threadIdx.x;
    if (i >= (long long)ROWS * EDIM) return;
    int e = (int)(i % EDIM);
    int t = (int)(i / EDIM);
    int n = t % NTOK;
    int b = t / NTOK;
    float v = (n == 0) ? cls_tok[e] : tok[(long long)(b * NPATCH + n - 1) * EDIM + e];
    h[i] = v + pos[(long long)n * EDIM + e];
}

// ================= host =================
static inline float* sym(const void* s)
{
    void* p = nullptr;
    cudaGetSymbolAddress(&p, s);
    return (float*)p;
}

extern "C" void kernel_launch(void* const* d_in, const int* in_sizes, int n_in,
                              void* d_out, int out_size)
{
    const float* x       = (const float*)d_in[0];
    const float* cls_tok = (const float*)d_in[1];
    const float* pos_emb = (const float*)d_in[2];
    const float* patch_w = (const float*)d_in[3];
    const float* patch_b = (const float*)d_in[4];
    const float* ln1_g   = (const float*)d_in[5];
    const float* ln1_b   = (const float*)d_in[6];
    const float* proj    = (const float*)d_in[7];
    const float* ln2_g   = (const float*)d_in[8];
    const float* ln2_b   = (const float*)d_in[9];
    const float* w1      = (const float*)d_in[10];
    const float* b1      = (const float*)d_in[11];
    const float* w2      = (const float*)d_in[12];
    const float* b2      = (const float*)d_in[13];
    const float* lnf_g   = (const float*)d_in[14];
    const float* lnf_b   = (const float*)d_in[15];
    const float* head_w  = (const float*)d_in[16];
    const float* head_b  = (const float*)d_in[17];
    float* out = (float*)d_out;

    float* h    = sym(g_h);
    float* y    = sym(g_y);
    float* tmp  = sym(g_tmp);
    float* lg   = sym(g_lg);
    float* qf   = sym(g_qf);
    float* kfT  = sym(g_kfT);
    float* yT   = sym(g_yT);
    float* kvT  = sym(g_kvT);
    float* diag = sym(g_diag);
    float* qmax = sym(g_qmax);
    float* den  = sym(g_den);
    float* ksum = sym(g_ksum);
    float* gmax = sym(g_gmax);
    float* clsb = sym(g_cls);
    float* w1T  = sym(g_w1T);
    float* w2T  = sym(g_w2T);

    float* pt  = tmp;             // [3136,768] im2col
    float* tok = tmp + 5000000;   // [3136,768] patch-embed out

    // --- weight transposes (w1T[l]: [3072,768], w2T[l]: [768,3072]) ---
    {
        dim3 blk(32, 8);
        transpose_tiled<<<dim3(96, 24, NLAYER), blk>>>(w1, w1T, EDIM, FDIM, EDIM,
            (long long)EDIM * FDIM, (long long)EDIM * FDIM);
        transpose_tiled<<<dim3(24, 96, NLAYER), blk>>>(w2, w2T, FDIM, EDIM, FDIM,
            (long long)EDIM * FDIM, (long long)EDIM * FDIM);
    }

    // --- patch embedding ---
    {
        long long tot = (long long)BSZ * NPATCH * 768;
        im2col_kernel<<<(unsigned)((tot + 255) / 256), 256>>>(x, pt);
        mma_gemm<<<dim3(6, 49, 1), 256>>>(pt, patch_w, tok,
            BSZ * NPATCH, 768, 768, EDIM, 0, 0, 0, 0, 0, 768,
            patch_b, nullptr, 0, 1);
        long long ht = (long long)ROWS * EDIM;
        assemble_kernel<<<(unsigned)((ht + 255) / 256), 256>>>(tok, cls_tok, pos_emb, h);
    }

    for (int l = 0; l < NLAYER; l++) {
        const float* prj = proj + (long long)l * MFEAT * EDIM;
        // LN1 + diag
        ln_kernel<<<(ROWS + 7) / 8, 256>>>(h, EDIM, y, EDIM,
            ln1_g + l * EDIM, ln1_b + l * EDIM, diag, ROWS);
        // logits = y @ proj^T (raw)
        mma_gemm<<<dim3(2, 50, 1), 256>>>(y, prj, lg,
            ROWS, EDIM, EDIM, MFEAT, 0, 0, 0, 0, 0, EDIM,
            nullptr, nullptr, 0, 0);
        lg_rowmax_kernel<<<ROWS, 256>>>(lg, diag, qmax);
        gmax_kernel<<<1, 256>>>(qmax, gmax);
        feat_kernel<<<(ROWS * MFEAT + 255) / 256, 256>>>(lg, qmax, gmax, qf, kfT);
        ksum_kernel<<<(BSZ * MFEAT * 32 + 255) / 256, 256>>>(kfT, ksum);
        // yT[b][e][t] (zero-padded t>=197)
        transpose_tiled<<<dim3(24, 7, BSZ), dim3(32, 8)>>>(y, yT, NTOK, EDIM, KPAD,
            (long long)NTOK * EDIM, (long long)EDIM * KPAD);
        // kvT[b] = yT[b] @ kfT[b]^T : [768,256], K=224
        mma_gemm<<<dim3(2, 12, BSZ), 256>>>(yT, kfT, kvT,
            EDIM, KPAD, KPAD, MFEAT,
            (long long)EDIM * KPAD, (long long)MFEAT * KPAD, (long long)EDIM * MFEAT,
            0, 0, KPAD, nullptr, nullptr, 0, 0);
        den_kernel<<<(ROWS + 7) / 8, 256>>>(qf, ksum, den);
        // h += (qf @ kvT^T) / den
        mma_gemm<<<dim3(6, 4, BSZ), 256>>>(qf, kvT, h,
            NTOK, MFEAT, MFEAT, EDIM,
            (long long)NTOK * MFEAT, (long long)EDIM * MFEAT, (long long)NTOK * EDIM,
            0, 0, MFEAT, nullptr, den, NTOK, 4 | 8);
        // LN2
        ln_kernel<<<(ROWS + 7) / 8, 256>>>(h, EDIM, y, EDIM,
            ln2_g + l * EDIM, ln2_b + l * EDIM, nullptr, ROWS);
        // hid = gelu(y @ w1 + b1)
        mma_gemm<<<dim3(24, 50, 1), 256>>>(y, w1T + (long long)l * EDIM * FDIM, tmp,
            ROWS, EDIM, EDIM, FDIM, 0, 0, 0, 0, 0, EDIM,
            b1 + l * FDIM, nullptr, 0, 1 | 2);
        // h += hid @ w2 + b2   (single K=3072, fused bias + residual accumulate)
        mma_gemm<<<dim3(6, 50, 1), 256>>>(tmp, w2T + (long long)l * EDIM * FDIM, h,
            ROWS, FDIM, FDIM, EDIM, 0, 0, 0,
            0, 0, FDIM, b2 + l * EDIM, nullptr, 0, 1 | 4);
    }

    // final LN on CLS tokens + head
    ln_kernel<<<2, 256>>>(h, (long long)NTOK * EDIM, clsb, EDIM, lnf_g, lnf_b, nullptr, BSZ);
    {
        dim3 grid(8, 1, 1);
        gemm_kernel<<<grid, 256>>>(clsb, head_w, out,
            BSZ, NC, EDIM, head_b, 1);
    }
}